// round 1
// baseline (speedup 1.0000x reference)
#include <cuda_runtime.h>
#include <cuda_bf16.h>

// ---------------------------------------------------------------------------
// Problem constants (fixed by the dataset)
// ---------------------------------------------------------------------------
constexpr int T   = 4096;   // B*S tokens
constexpr int H   = 1024;
constexpr int F   = 2048;
constexpr int E   = 8;
constexpr int CAP = 640;    // ceil(1.25 * 4096 / 8)

// ---------------------------------------------------------------------------
// Scratch (static device globals — no allocations allowed)
// ---------------------------------------------------------------------------
__device__ float d_tokens_ln[(size_t)T * H];      // 16 MB
__device__ float d_xin[(size_t)E * CAP * H];      // 20 MB
__device__ float d_g[(size_t)E * CAP * F];        // 40 MB
__device__ float d_u[(size_t)E * CAP * F];        // 40 MB
__device__ float d_eout[(size_t)E * CAP * H];     // 20 MB
__device__ int   d_sel[E * CAP];
__device__ int   d_valid[E * CAP];
__device__ int   d_idx[T * 2];
__device__ float d_wts[T * 2];

// ---------------------------------------------------------------------------
// Kernel A: LayerNorm + router logits + softmax + top-2 (one block per token)
// ---------------------------------------------------------------------------
__global__ void __launch_bounds__(256) ln_router_kernel(
    const float* __restrict__ x, const float* __restrict__ rw,
    const float* __restrict__ gamma, const float* __restrict__ beta)
{
    int t   = blockIdx.x;
    int tid = threadIdx.x;

    const float4 v  = ((const float4*)(x + (size_t)t * H))[tid];

    __shared__ float sdata[256];
    float s = v.x + v.y + v.z + v.w;
    sdata[tid] = s; __syncthreads();
    #pragma unroll
    for (int o = 128; o > 0; o >>= 1) {
        if (tid < o) sdata[tid] += sdata[tid + o];
        __syncthreads();
    }
    float mu = sdata[0] * (1.0f / H);
    __syncthreads();

    float dx0 = v.x - mu, dx1 = v.y - mu, dx2 = v.z - mu, dx3 = v.w - mu;
    s = dx0 * dx0 + dx1 * dx1 + dx2 * dx2 + dx3 * dx3;
    sdata[tid] = s; __syncthreads();
    #pragma unroll
    for (int o = 128; o > 0; o >>= 1) {
        if (tid < o) sdata[tid] += sdata[tid + o];
        __syncthreads();
    }
    float var  = sdata[0] * (1.0f / H);
    float rstd = rsqrtf(var + 1e-5f);
    __syncthreads();

    float4 g4 = ((const float4*)gamma)[tid];
    float4 b4 = ((const float4*)beta)[tid];
    float tl[4];
    tl[0] = dx0 * rstd * g4.x + b4.x;
    tl[1] = dx1 * rstd * g4.y + b4.y;
    tl[2] = dx2 * rstd * g4.z + b4.z;
    tl[3] = dx3 * rstd * g4.w + b4.w;
    ((float4*)(d_tokens_ln + (size_t)t * H))[tid] =
        make_float4(tl[0], tl[1], tl[2], tl[3]);

    // router logits: partial per-thread over its 4 h-values
    int h0 = tid * 4;
    float acc[E];
    #pragma unroll
    for (int e = 0; e < E; e++) acc[e] = 0.0f;
    #pragma unroll
    for (int j = 0; j < 4; j++) {
        const float* rwr = rw + (size_t)(h0 + j) * E;
        #pragma unroll
        for (int e = 0; e < E; e++) acc[e] += tl[j] * rwr[e];
    }
    // deterministic reduction: warp shuffle then shared
    #pragma unroll
    for (int off = 16; off > 0; off >>= 1)
        #pragma unroll
        for (int e = 0; e < E; e++)
            acc[e] += __shfl_down_sync(0xffffffffu, acc[e], off);

    __shared__ float wlog[8][E];
    int warp = tid >> 5, lane = tid & 31;
    if (lane == 0)
        #pragma unroll
        for (int e = 0; e < E; e++) wlog[warp][e] = acc[e];
    __syncthreads();

    if (tid == 0) {
        float lg[E];
        #pragma unroll
        for (int e = 0; e < E; e++) {
            float sv = 0.0f;
            #pragma unroll
            for (int w = 0; w < 8; w++) sv += wlog[w][e];
            lg[e] = sv;
        }
        float mx = lg[0];
        #pragma unroll
        for (int e = 1; e < E; e++) mx = fmaxf(mx, lg[e]);
        float p[E];
        #pragma unroll
        for (int e = 0; e < E; e++) p[e] = expf(lg[e] - mx);

        int i0 = 0; float b0 = p[0];
        #pragma unroll
        for (int e = 1; e < E; e++) if (p[e] > b0) { b0 = p[e]; i0 = e; }
        int i1 = -1; float b1 = -1.0f;
        #pragma unroll
        for (int e = 0; e < E; e++)
            if (e != i0 && p[e] > b1) { b1 = p[e]; i1 = e; }

        float inv = 1.0f / (b0 + b1);
        d_idx[2 * t]     = i0;
        d_idx[2 * t + 1] = i1;
        d_wts[2 * t]     = b0 * inv;
        d_wts[2 * t + 1] = b1 * inv;
    }
}

// ---------------------------------------------------------------------------
// Kernel B: capacity assignment (stable: selected tokens in order, then rest)
// One block per expert.
// ---------------------------------------------------------------------------
__global__ void __launch_bounds__(1024) assign_kernel()
{
    int e   = blockIdx.x;
    int tid = threadIdx.x;
    int lane = tid & 31, warp = tid >> 5;

    __shared__ int warpCnt[32];
    __shared__ int s_totalSel, s_runSel, s_runUnsel, s_chunkSel;

    // phase 1: total selected count
    int cnt = 0;
    for (int t = tid; t < T; t += 1024) {
        int m = (d_idx[2 * t] == e) | (d_idx[2 * t + 1] == e);
        cnt += m;
    }
    #pragma unroll
    for (int off = 16; off > 0; off >>= 1)
        cnt += __shfl_down_sync(0xffffffffu, cnt, off);
    if (lane == 0) warpCnt[warp] = cnt;
    __syncthreads();
    if (tid == 0) {
        int sv = 0;
        for (int w = 0; w < 32; w++) sv += warpCnt[w];
        s_totalSel = sv; s_runSel = 0; s_runUnsel = 0;
    }
    __syncthreads();
    int totalSel = s_totalSel;

    // phase 2: stable placement
    for (int base = 0; base < T; base += 1024) {
        int t = base + tid;
        int m = (d_idx[2 * t] == e) | (d_idx[2 * t + 1] == e);
        unsigned bal = __ballot_sync(0xffffffffu, m);
        int wpre = __popc(bal & ((1u << lane) - 1u));
        if (lane == 0) warpCnt[warp] = __popc(bal);
        __syncthreads();
        if (tid == 0) {
            int sv = 0;
            for (int w = 0; w < 32; w++) { int c = warpCnt[w]; warpCnt[w] = sv; sv += c; }
            s_chunkSel = sv;
        }
        __syncthreads();
        int selPre = warpCnt[warp] + wpre;        // exclusive prefix within chunk
        int rs = s_runSel, ru = s_runUnsel;
        int pos = m ? (rs + selPre)
                    : (totalSel + ru + (tid - selPre));
        if (pos < CAP) {
            d_sel[e * CAP + pos]   = t;
            d_valid[e * CAP + pos] = m;
        }
        __syncthreads();
        if (tid == 0) {
            s_runSel   = rs + s_chunkSel;
            s_runUnsel = ru + (1024 - s_chunkSel);
        }
        __syncthreads();
    }
}

// ---------------------------------------------------------------------------
// Kernel C: gather xin[e,c,:] = valid ? tokens_ln[sel] : 0
// ---------------------------------------------------------------------------
__global__ void __launch_bounds__(256) gather_kernel()
{
    int i  = blockIdx.x * 256 + threadIdx.x;    // float4 index
    int h4 = i & (H / 4 - 1);
    int ec = i >> 8;                            // / (H/4)
    int v  = d_valid[ec];
    int s  = d_sel[ec];
    float4 out = make_float4(0.f, 0.f, 0.f, 0.f);
    if (v) out = ((const float4*)d_tokens_ln)[(size_t)s * (H / 4) + h4];
    ((float4*)d_xin)[i] = out;
}

// ---------------------------------------------------------------------------
// SGEMM body: 128x128 block tile, 8x8 per-thread, BK=8, 256 threads.
// FUSED: A element = silu(A[i]) * A2[i] (for the down-proj).
// ---------------------------------------------------------------------------
__device__ __forceinline__ float silu_f(float v) { return v / (1.0f + __expf(-v)); }

template <bool FUSED>
__device__ __forceinline__ void sgemm_body(
    const float* __restrict__ A, const float* __restrict__ A2,
    const float* __restrict__ B, float* __restrict__ C, int N, int K)
{
    constexpr int BM = 128, BN = 128, BK = 8;
    __shared__ __align__(16) float As[BK][BM];
    __shared__ __align__(16) float Bs[BK][BN];

    int tid  = threadIdx.x;
    int m0   = blockIdx.y * BM, n0 = blockIdx.x * BN;
    int arow = tid >> 1,  acol = (tid & 1) * 4;
    int brow = tid >> 5,  bcol = (tid & 31) * 4;
    int tx   = tid & 15,  ty   = tid >> 4;

    float acc[8][8];
    #pragma unroll
    for (int m = 0; m < 8; m++)
        #pragma unroll
        for (int n = 0; n < 8; n++) acc[m][n] = 0.0f;

    for (int k0 = 0; k0 < K; k0 += BK) {
        float4 a = *(const float4*)(A + (size_t)(m0 + arow) * K + k0 + acol);
        if (FUSED) {
            float4 u = *(const float4*)(A2 + (size_t)(m0 + arow) * K + k0 + acol);
            a.x = silu_f(a.x) * u.x;
            a.y = silu_f(a.y) * u.y;
            a.z = silu_f(a.z) * u.z;
            a.w = silu_f(a.w) * u.w;
        }
        As[acol + 0][arow] = a.x;
        As[acol + 1][arow] = a.y;
        As[acol + 2][arow] = a.z;
        As[acol + 3][arow] = a.w;
        *(float4*)&Bs[brow][bcol] =
            *(const float4*)(B + (size_t)(k0 + brow) * N + n0 + bcol);
        __syncthreads();

        #pragma unroll
        for (int k = 0; k < BK; k++) {
            float4 ra0 = *(const float4*)&As[k][ty * 8];
            float4 ra1 = *(const float4*)&As[k][ty * 8 + 4];
            float4 rb0 = *(const float4*)&Bs[k][tx * 8];
            float4 rb1 = *(const float4*)&Bs[k][tx * 8 + 4];
            float ra[8] = {ra0.x, ra0.y, ra0.z, ra0.w, ra1.x, ra1.y, ra1.z, ra1.w};
            float rb[8] = {rb0.x, rb0.y, rb0.z, rb0.w, rb1.x, rb1.y, rb1.z, rb1.w};
            #pragma unroll
            for (int m = 0; m < 8; m++)
                #pragma unroll
                for (int n = 0; n < 8; n++)
                    acc[m][n] = fmaf(ra[m], rb[n], acc[m][n]);
        }
        __syncthreads();
    }

    #pragma unroll
    for (int m = 0; m < 8; m++) {
        float* crow = C + (size_t)(m0 + ty * 8 + m) * N + n0 + tx * 8;
        *(float4*)(crow)     = make_float4(acc[m][0], acc[m][1], acc[m][2], acc[m][3]);
        *(float4*)(crow + 4) = make_float4(acc[m][4], acc[m][5], acc[m][6], acc[m][7]);
    }
}

// GEMM1: gate & up projections.  grid = (F/128=16, CAP/128=5, E*2)
__global__ void __launch_bounds__(256) gemm_gateup_kernel(
    const float* __restrict__ Wg, const float* __restrict__ Wu)
{
    int z = blockIdx.z;
    int e = z >> 1, up = z & 1;
    const float* A = d_xin + (size_t)e * CAP * H;
    const float* B = (up ? Wu : Wg) + (size_t)e * H * F;
    float*       C = (up ? d_u : d_g) + (size_t)e * CAP * F;
    sgemm_body<false>(A, nullptr, B, C, F, H);
}

// GEMM2: down projection with fused silu(g)*u A-load. grid = (H/128=8, 5, E)
__global__ void __launch_bounds__(256) gemm_down_kernel(const float* __restrict__ Wd)
{
    int e = blockIdx.z;
    const float* A  = d_g + (size_t)e * CAP * F;
    const float* A2 = d_u + (size_t)e * CAP * F;
    const float* B  = Wd + (size_t)e * F * H;
    float*       C  = d_eout + (size_t)e * CAP * H;
    sgemm_body<true>(A, A2, B, C, H, F);
}

// ---------------------------------------------------------------------------
// Kernel F: combine  out[t] = x[t] + w0*eout[i0, slot] + w1*eout[i1, slot]
// slot = min(t, CAP-1)   (exactly as the reference does)
// ---------------------------------------------------------------------------
__global__ void __launch_bounds__(256) combine_kernel(
    const float* __restrict__ x, float* __restrict__ out)
{
    int i  = blockIdx.x * 256 + threadIdx.x;   // float4 index over T*H/4
    int h4 = i & (H / 4 - 1);
    int t  = i >> 8;
    int slot = min(t, CAP - 1);
    int i0 = d_idx[2 * t], i1 = d_idx[2 * t + 1];
    float w0 = d_wts[2 * t], w1 = d_wts[2 * t + 1];

    const float4* e4 = (const float4*)d_eout;
    float4 a  = ((const float4*)x)[i];
    float4 g0 = e4[((size_t)i0 * CAP + slot) * (H / 4) + h4];
    float4 g1 = e4[((size_t)i1 * CAP + slot) * (H / 4) + h4];
    float4 o;
    o.x = a.x + w0 * g0.x + w1 * g1.x;
    o.y = a.y + w0 * g0.y + w1 * g1.y;
    o.z = a.z + w0 * g0.z + w1 * g1.z;
    o.w = a.w + w0 * g0.w + w1 * g1.w;
    ((float4*)out)[i] = o;
}

// ---------------------------------------------------------------------------
// Launch
// ---------------------------------------------------------------------------
extern "C" void kernel_launch(void* const* d_in, const int* in_sizes, int n_in,
                              void* d_out, int out_size)
{
    const float* x     = (const float*)d_in[0];
    const float* rw    = (const float*)d_in[1];
    const float* wg    = (const float*)d_in[2];
    const float* wu    = (const float*)d_in[3];
    const float* wd    = (const float*)d_in[4];
    const float* gamma = (const float*)d_in[5];
    const float* beta  = (const float*)d_in[6];
    float*       out   = (float*)d_out;

    ln_router_kernel<<<T, 256>>>(x, rw, gamma, beta);
    assign_kernel<<<E, 1024>>>();
    gather_kernel<<<(E * CAP * H / 4) / 256, 256>>>();
    gemm_gateup_kernel<<<dim3(F / 128, CAP / 128, E * 2), 256>>>(wg, wu);
    gemm_down_kernel<<<dim3(H / 128, CAP / 128, E), 256>>>(wd);
    combine_kernel<<<(T * H / 4) / 256, 256>>>(x, out);
}

// round 3
// speedup vs baseline: 2.1422x; 2.1422x over previous
#include <cuda_runtime.h>
#include <cuda_bf16.h>
#include <cstdint>

// ---------------------------------------------------------------------------
// Problem constants
// ---------------------------------------------------------------------------
constexpr int T   = 4096;
constexpr int H   = 1024;
constexpr int F   = 2048;
constexpr int E   = 8;
constexpr int CAP = 640;

constexpr int K1  = 3 * H;   // 3072  (triple-split K for GEMM1)
constexpr int K2  = 3 * F;   // 6144  (triple-split K for GEMM2)
constexpr int NB1 = 2 * F;   // 4096  interleaved gate/up rows
constexpr int NB2 = H;       // 1024

// ---------------------------------------------------------------------------
// Scratch (static device globals — allocation-free rule)
// ---------------------------------------------------------------------------
__device__ float d_tokens_ln[(size_t)T * H];
__device__ int   d_sel[E * CAP];
__device__ int   d_valid[E * CAP];
__device__ int   d_idx[T * 2];
__device__ float d_wts[T * 2];
__device__ __align__(16) __nv_bfloat16 d_xin_bf[(size_t)E * CAP * K1];
__device__ __align__(16) __nv_bfloat16 d_wgu_bf[(size_t)E * NB1 * K1];
__device__ __align__(16) __nv_bfloat16 d_wd_bf [(size_t)E * NB2 * K2];
__device__ __align__(16) __nv_bfloat16 d_act_bf[(size_t)E * CAP * K2];
__device__ float d_eout[(size_t)E * CAP * H];

// ---------------------------------------------------------------------------
// PTX helpers
// ---------------------------------------------------------------------------
__device__ __forceinline__ uint32_t smem_u32(const void* p) {
    uint32_t a;
    asm("{ .reg .u64 t; cvta.to.shared.u64 t, %1; cvt.u32.u64 %0, t; }" : "=r"(a) : "l"(p));
    return a;
}
#define CP_ASYNC16(dst, src) \
    asm volatile("cp.async.cg.shared.global [%0], [%1], 16;" :: "r"(dst), "l"(src))
#define CP_COMMIT() asm volatile("cp.async.commit_group;" ::: "memory")
#define CP_WAIT2()  asm volatile("cp.async.wait_group 2;" ::: "memory")

__device__ __forceinline__ void ldmx4(uint32_t& r0, uint32_t& r1, uint32_t& r2,
                                      uint32_t& r3, uint32_t a) {
    asm volatile("ldmatrix.sync.aligned.m8n8.x4.shared.b16 {%0,%1,%2,%3}, [%4];"
                 : "=r"(r0), "=r"(r1), "=r"(r2), "=r"(r3) : "r"(a));
}
__device__ __forceinline__ void mma_bf16(float* c, uint32_t a0, uint32_t a1,
                                         uint32_t a2, uint32_t a3,
                                         uint32_t b0, uint32_t b1) {
    asm volatile(
        "mma.sync.aligned.m16n8k16.row.col.f32.bf16.bf16.f32 "
        "{%0,%1,%2,%3}, {%4,%5,%6,%7}, {%8,%9}, {%0,%1,%2,%3};"
        : "+f"(c[0]), "+f"(c[1]), "+f"(c[2]), "+f"(c[3])
        : "r"(a0), "r"(a1), "r"(a2), "r"(a3), "r"(b0), "r"(b1));
}

// ---------------------------------------------------------------------------
// Kernel A: LayerNorm + router + top-2 (one block / token)
// ---------------------------------------------------------------------------
__global__ void __launch_bounds__(256) ln_router_kernel(
    const float* __restrict__ x, const float* __restrict__ rw,
    const float* __restrict__ gamma, const float* __restrict__ beta)
{
    int t   = blockIdx.x;
    int tid = threadIdx.x;
    const float4 v = ((const float4*)(x + (size_t)t * H))[tid];

    __shared__ float sdata[256];
    float s = v.x + v.y + v.z + v.w;
    sdata[tid] = s; __syncthreads();
    #pragma unroll
    for (int o = 128; o > 0; o >>= 1) { if (tid < o) sdata[tid] += sdata[tid + o]; __syncthreads(); }
    float mu = sdata[0] * (1.0f / H);
    __syncthreads();

    float dx0 = v.x - mu, dx1 = v.y - mu, dx2 = v.z - mu, dx3 = v.w - mu;
    s = dx0 * dx0 + dx1 * dx1 + dx2 * dx2 + dx3 * dx3;
    sdata[tid] = s; __syncthreads();
    #pragma unroll
    for (int o = 128; o > 0; o >>= 1) { if (tid < o) sdata[tid] += sdata[tid + o]; __syncthreads(); }
    float rstd = rsqrtf(sdata[0] * (1.0f / H) + 1e-5f);
    __syncthreads();

    float4 g4 = ((const float4*)gamma)[tid];
    float4 b4 = ((const float4*)beta)[tid];
    float tl[4];
    tl[0] = dx0 * rstd * g4.x + b4.x;
    tl[1] = dx1 * rstd * g4.y + b4.y;
    tl[2] = dx2 * rstd * g4.z + b4.z;
    tl[3] = dx3 * rstd * g4.w + b4.w;
    ((float4*)(d_tokens_ln + (size_t)t * H))[tid] = make_float4(tl[0], tl[1], tl[2], tl[3]);

    int h0 = tid * 4;
    float acc[E];
    #pragma unroll
    for (int e = 0; e < E; e++) acc[e] = 0.0f;
    #pragma unroll
    for (int j = 0; j < 4; j++) {
        const float* rwr = rw + (size_t)(h0 + j) * E;
        #pragma unroll
        for (int e = 0; e < E; e++) acc[e] += tl[j] * rwr[e];
    }
    #pragma unroll
    for (int off = 16; off > 0; off >>= 1)
        #pragma unroll
        for (int e = 0; e < E; e++)
            acc[e] += __shfl_down_sync(0xffffffffu, acc[e], off);

    __shared__ float wlog[8][E];
    int warp = tid >> 5, lane = tid & 31;
    if (lane == 0)
        #pragma unroll
        for (int e = 0; e < E; e++) wlog[warp][e] = acc[e];
    __syncthreads();

    if (tid == 0) {
        float lg[E];
        #pragma unroll
        for (int e = 0; e < E; e++) {
            float sv = 0.0f;
            #pragma unroll
            for (int w = 0; w < 8; w++) sv += wlog[w][e];
            lg[e] = sv;
        }
        float mx = lg[0];
        #pragma unroll
        for (int e = 1; e < E; e++) mx = fmaxf(mx, lg[e]);
        float p[E];
        #pragma unroll
        for (int e = 0; e < E; e++) p[e] = expf(lg[e] - mx);
        int i0 = 0; float b0 = p[0];
        #pragma unroll
        for (int e = 1; e < E; e++) if (p[e] > b0) { b0 = p[e]; i0 = e; }
        int i1 = -1; float b1 = -1.0f;
        #pragma unroll
        for (int e = 0; e < E; e++) if (e != i0 && p[e] > b1) { b1 = p[e]; i1 = e; }
        float inv = 1.0f / (b0 + b1);
        d_idx[2 * t] = i0; d_idx[2 * t + 1] = i1;
        d_wts[2 * t] = b0 * inv; d_wts[2 * t + 1] = b1 * inv;
    }
}

// ---------------------------------------------------------------------------
// Kernel B: capacity assignment (stable), one block / expert
// ---------------------------------------------------------------------------
__global__ void __launch_bounds__(1024) assign_kernel()
{
    int e = blockIdx.x, tid = threadIdx.x;
    int lane = tid & 31, warp = tid >> 5;
    __shared__ int warpCnt[32];
    __shared__ int s_totalSel, s_runSel, s_runUnsel, s_chunkSel;

    int cnt = 0;
    for (int t = tid; t < T; t += 1024)
        cnt += (d_idx[2 * t] == e) | (d_idx[2 * t + 1] == e);
    #pragma unroll
    for (int off = 16; off > 0; off >>= 1) cnt += __shfl_down_sync(0xffffffffu, cnt, off);
    if (lane == 0) warpCnt[warp] = cnt;
    __syncthreads();
    if (tid == 0) {
        int sv = 0;
        for (int w = 0; w < 32; w++) sv += warpCnt[w];
        s_totalSel = sv; s_runSel = 0; s_runUnsel = 0;
    }
    __syncthreads();
    int totalSel = s_totalSel;

    for (int base = 0; base < T; base += 1024) {
        int t = base + tid;
        int m = (d_idx[2 * t] == e) | (d_idx[2 * t + 1] == e);
        unsigned bal = __ballot_sync(0xffffffffu, m);
        int wpre = __popc(bal & ((1u << lane) - 1u));
        if (lane == 0) warpCnt[warp] = __popc(bal);
        __syncthreads();
        if (tid == 0) {
            int sv = 0;
            for (int w = 0; w < 32; w++) { int c = warpCnt[w]; warpCnt[w] = sv; sv += c; }
            s_chunkSel = sv;
        }
        __syncthreads();
        int selPre = warpCnt[warp] + wpre;
        int rs = s_runSel, ru = s_runUnsel;
        int pos = m ? (rs + selPre) : (totalSel + ru + (tid - selPre));
        if (pos < CAP) { d_sel[e * CAP + pos] = t; d_valid[e * CAP + pos] = m; }
        __syncthreads();
        if (tid == 0) { s_runSel = rs + s_chunkSel; s_runUnsel = ru + (1024 - s_chunkSel); }
        __syncthreads();
    }
}

// ---------------------------------------------------------------------------
// Kernel C: gather + triple-split convert: xin_bf[ec][3h] = (hi,hi,lo)
// ---------------------------------------------------------------------------
__global__ void __launch_bounds__(128) gather_convert_kernel()
{
    int ec = blockIdx.x, tid = threadIdx.x;
    int v = d_valid[ec], s = d_sel[ec];
    float4 a = make_float4(0.f,0.f,0.f,0.f), b = a;
    if (v) {
        const float4* src = (const float4*)(d_tokens_ln + (size_t)s * H);
        a = src[tid * 2]; b = src[tid * 2 + 1];
    }
    float vv[8] = {a.x, a.y, a.z, a.w, b.x, b.y, b.z, b.w};
    alignas(16) __nv_bfloat16 o[24];
    #pragma unroll
    for (int j = 0; j < 8; j++) {
        __nv_bfloat16 hi = __float2bfloat16(vv[j]);
        __nv_bfloat16 lo = __float2bfloat16(vv[j] - __bfloat162float(hi));
        o[3*j] = hi; o[3*j+1] = hi; o[3*j+2] = lo;
    }
    uint4* dst = (uint4*)(d_xin_bf + (size_t)ec * K1 + tid * 24);
    const uint4* so = (const uint4*)o;
    dst[0] = so[0]; dst[1] = so[1]; dst[2] = so[2];
}

// ---------------------------------------------------------------------------
// Kernel D: gate/up weight transpose + split:  [E][H][F] -> [E][2F][3H]
// row n = 2f+s (s=0 gate, 1 up); triple (hi, lo, hi)
// ---------------------------------------------------------------------------
__global__ void __launch_bounds__(256) conv_gateup_kernel(
    const float* __restrict__ wg, const float* __restrict__ wu)
{
    int f0 = blockIdx.x * 32, h0 = blockIdx.y * 64, e = blockIdx.z;
    __shared__ float sg[32][65], su[32][65];
    int t = threadIdx.x, fi = t & 31, hr = t >> 5;
    #pragma unroll
    for (int it = 0; it < 8; it++) {
        int hl = hr + it * 8;
        size_t base = ((size_t)e * H + h0 + hl) * F + f0 + fi;
        sg[fi][hl] = wg[base];
        su[fi][hl] = wu[base];
    }
    __syncthreads();
    for (int u = t; u < 64 * 24; u += 256) {
        int r = u / 24, unit = u % 24;
        int fl = r >> 1, s = r & 1;
        const float (*sm)[65] = s ? su : sg;
        alignas(16) __nv_bfloat16 o[8];
        #pragma unroll
        for (int c = 0; c < 8; c++) {
            int cc = unit * 8 + c; int k = cc / 3, rm = cc - 3 * k;
            float v = sm[fl][k];
            __nv_bfloat16 hi = __float2bfloat16(v);
            o[c] = (rm == 1) ? __float2bfloat16(v - __bfloat162float(hi)) : hi;
        }
        *(uint4*)(d_wgu_bf + ((size_t)e * NB1 + 2 * f0 + r) * K1 + 3 * h0 + unit * 8) =
            *(const uint4*)o;
    }
}

// ---------------------------------------------------------------------------
// Kernel E: down weight transpose + split: [E][F][H] -> [E][H][3F], (hi,lo,hi)
// ---------------------------------------------------------------------------
__global__ void __launch_bounds__(256) conv_down_kernel(const float* __restrict__ wd)
{
    int f0 = blockIdx.x * 64, h0 = blockIdx.y * 32, e = blockIdx.z;
    __shared__ float sd[32][65];
    int t = threadIdx.x, hl = t & 31, fr = t >> 5;
    #pragma unroll
    for (int it = 0; it < 8; it++) {
        int fl = fr + it * 8;
        sd[hl][fl] = wd[((size_t)e * F + f0 + fl) * H + h0 + hl];
    }
    __syncthreads();
    for (int u = t; u < 32 * 24; u += 256) {
        int r = u / 24, unit = u % 24;
        alignas(16) __nv_bfloat16 o[8];
        #pragma unroll
        for (int c = 0; c < 8; c++) {
            int cc = unit * 8 + c; int k = cc / 3, rm = cc - 3 * k;
            float v = sd[r][k];
            __nv_bfloat16 hi = __float2bfloat16(v);
            o[c] = (rm == 1) ? __float2bfloat16(v - __bfloat162float(hi)) : hi;
        }
        *(uint4*)(d_wd_bf + ((size_t)e * NB2 + h0 + r) * K2 + 3 * f0 + unit * 8) =
            *(const uint4*)o;
    }
}

// ---------------------------------------------------------------------------
// mma.sync bf16 GEMM: 128x128 CTA tile, BK=32, 8 warps (32x64 warp tile),
// 3-stage cp.async pipeline, smem rows padded to 80B (conflict-free ldmatrix).
// GATEUP=true : epilogue silu(gate)*up -> triple-split -> d_act_bf
// GATEUP=false: epilogue fp32 -> d_eout
// ---------------------------------------------------------------------------
constexpr int STAGE_BYTES = 20480;            // A 128*80 + B 128*80
constexpr int GEMM_SMEM   = 3 * STAGE_BYTES;  // 61440

template<int KT, int NB, bool GATEUP>
__global__ void __launch_bounds__(256, 2) moe_gemm_kernel()
{
    constexpr int NC = KT / 32;
    extern __shared__ char smem_raw[];
    uint32_t sb = smem_u32(smem_raw);
    int tid = threadIdx.x, wid = tid >> 5, lane = tid & 31;
    int e = blockIdx.z, m0 = blockIdx.y * 128, n0 = blockIdx.x * 128;
    int wm0 = (wid & 3) * 32, wn0 = (wid >> 2) * 64;

    const __nv_bfloat16* Arow =
        (GATEUP ? d_xin_bf : d_act_bf) + ((size_t)e * CAP + m0) * KT;
    const __nv_bfloat16* Brow =
        (GATEUP ? d_wgu_bf : d_wd_bf) + ((size_t)e * NB + n0) * KT;

    float acc[2][8][4] = {};

    auto loadst = [&](int s, int chunk) {
        uint32_t abase = sb + s * STAGE_BYTES;
        uint32_t bbase = abase + 10240;
        const char* ag = (const char*)Arow + chunk * 64;
        const char* bg = (const char*)Brow + chunk * 64;
        #pragma unroll
        for (int it = 0; it < 2; it++) {
            int u = tid + it * 256; int row = u >> 2, c = u & 3;
            CP_ASYNC16(abase + row * 80 + c * 16, ag + (size_t)row * (KT * 2) + c * 16);
        }
        #pragma unroll
        for (int it = 0; it < 2; it++) {
            int u = tid + it * 256; int row = u >> 2, c = u & 3;
            CP_ASYNC16(bbase + row * 80 + c * 16, bg + (size_t)row * (KT * 2) + c * 16);
        }
        CP_COMMIT();
    };

    #pragma unroll
    for (int s = 0; s < 3; s++) loadst(s, s);

    for (int i = 0; i < NC; i++) {
        int s = i % 3;
        CP_WAIT2();
        __syncthreads();
        uint32_t abase = sb + s * STAGE_BYTES;
        uint32_t bbase = abase + 10240;
        #pragma unroll
        for (int kk = 0; kk < 2; kk++) {
            uint32_t a[2][4];
            #pragma unroll
            for (int ms = 0; ms < 2; ms++) {
                uint32_t ad = abase + (wm0 + ms * 16 + (lane & 15)) * 80
                            + (kk * 2 + (lane >> 4)) * 16;
                ldmx4(a[ms][0], a[ms][1], a[ms][2], a[ms][3], ad);
            }
            #pragma unroll
            for (int np = 0; np < 4; np++) {
                uint32_t b0, b1, b2, b3;
                uint32_t bd = bbase + (wn0 + np * 16 + (lane & 7) + ((lane >> 4) << 3)) * 80
                            + (kk * 2 + ((lane >> 3) & 1)) * 16;
                ldmx4(b0, b1, b2, b3, bd);
                #pragma unroll
                for (int ms = 0; ms < 2; ms++) {
                    mma_bf16(acc[ms][np * 2],     a[ms][0], a[ms][1], a[ms][2], a[ms][3], b0, b1);
                    mma_bf16(acc[ms][np * 2 + 1], a[ms][0], a[ms][1], a[ms][2], a[ms][3], b2, b3);
                }
            }
        }
        __syncthreads();
        if (i + 3 < NC) loadst(s, i + 3); else CP_COMMIT();
    }

    // -------- epilogue --------
    #pragma unroll
    for (int ms = 0; ms < 2; ms++) {
        #pragma unroll
        for (int np = 0; np < 8; np++) {
            int r0 = m0 + wm0 + ms * 16 + (lane >> 2);
            int nc = n0 + wn0 + np * 8 + (lane & 3) * 2;
            if (GATEUP) {
                int f = nc >> 1;
                #pragma unroll
                for (int h = 0; h < 2; h++) {
                    int row = r0 + h * 8;
                    float g  = acc[ms][np][2 * h];
                    float uu = acc[ms][np][2 * h + 1];
                    float av = (g / (1.0f + __expf(-g))) * uu;
                    __nv_bfloat16 hi = __float2bfloat16(av);
                    __nv_bfloat16 lo = __float2bfloat16(av - __bfloat162float(hi));
                    __nv_bfloat16* p = d_act_bf + ((size_t)e * CAP + row) * K2 + 3 * f;
                    p[0] = hi; p[1] = hi; p[2] = lo;
                }
            } else {
                #pragma unroll
                for (int h = 0; h < 2; h++) {
                    int row = r0 + h * 8;
                    float2* p = (float2*)(d_eout + ((size_t)e * CAP + row) * H + nc);
                    *p = make_float2(acc[ms][np][2 * h], acc[ms][np][2 * h + 1]);
                }
            }
        }
    }
}

// ---------------------------------------------------------------------------
// Kernel F: combine  out[t] = x[t] + w0*eout[i0,slot] + w1*eout[i1,slot]
// ---------------------------------------------------------------------------
__global__ void __launch_bounds__(256) combine_kernel(
    const float* __restrict__ x, float* __restrict__ out)
{
    int i = blockIdx.x * 256 + threadIdx.x;
    int h4 = i & (H / 4 - 1);
    int t  = i >> 8;
    int slot = min(t, CAP - 1);
    int i0 = d_idx[2 * t], i1 = d_idx[2 * t + 1];
    float w0 = d_wts[2 * t], w1 = d_wts[2 * t + 1];
    const float4* e4 = (const float4*)d_eout;
    float4 a  = ((const float4*)x)[i];
    float4 g0 = e4[((size_t)i0 * CAP + slot) * (H / 4) + h4];
    float4 g1 = e4[((size_t)i1 * CAP + slot) * (H / 4) + h4];
    float4 o;
    o.x = a.x + w0 * g0.x + w1 * g1.x;
    o.y = a.y + w0 * g0.y + w1 * g1.y;
    o.z = a.z + w0 * g0.z + w1 * g1.z;
    o.w = a.w + w0 * g0.w + w1 * g1.w;
    ((float4*)out)[i] = o;
}

// ---------------------------------------------------------------------------
// Launch
// ---------------------------------------------------------------------------
extern "C" void kernel_launch(void* const* d_in, const int* in_sizes, int n_in,
                              void* d_out, int out_size)
{
    const float* x     = (const float*)d_in[0];
    const float* rw    = (const float*)d_in[1];
    const float* wg    = (const float*)d_in[2];
    const float* wu    = (const float*)d_in[3];
    const float* wd    = (const float*)d_in[4];
    const float* gamma = (const float*)d_in[5];
    const float* beta  = (const float*)d_in[6];
    float*       out   = (float*)d_out;

    cudaFuncSetAttribute(moe_gemm_kernel<K1, NB1, true>,
                         cudaFuncAttributeMaxDynamicSharedMemorySize, GEMM_SMEM);
    cudaFuncSetAttribute(moe_gemm_kernel<K2, NB2, false>,
                         cudaFuncAttributeMaxDynamicSharedMemorySize, GEMM_SMEM);

    ln_router_kernel<<<T, 256>>>(x, rw, gamma, beta);
    assign_kernel<<<E, 1024>>>();
    conv_gateup_kernel<<<dim3(F / 32, H / 64, E), 256>>>(wg, wu);
    conv_down_kernel<<<dim3(F / 64, H / 32, E), 256>>>(wd);
    gather_convert_kernel<<<E * CAP, 128>>>();
    moe_gemm_kernel<K1, NB1, true ><<<dim3(NB1 / 128, CAP / 128, E), 256, GEMM_SMEM>>>();
    moe_gemm_kernel<K2, NB2, false><<<dim3(NB2 / 128, CAP / 128, E), 256, GEMM_SMEM>>>();
    combine_kernel<<<(T * H / 4) / 256, 256>>>(x, out);
}

// round 4
// speedup vs baseline: 2.2925x; 1.0701x over previous
#include <cuda_runtime.h>
#include <cuda_bf16.h>
#include <cstdint>

// ---------------------------------------------------------------------------
// Problem constants
// ---------------------------------------------------------------------------
constexpr int T   = 4096;
constexpr int H   = 1024;
constexpr int F   = 2048;
constexpr int E   = 8;
constexpr int CAP = 640;

constexpr int K1  = 3 * H;   // 3072
constexpr int K2  = 3 * F;   // 6144
constexpr int NB1 = 2 * F;   // 4096
constexpr int NB2 = H;       // 1024

// ---------------------------------------------------------------------------
// Scratch
// ---------------------------------------------------------------------------
__device__ float d_tokens_ln[(size_t)T * H];
__device__ int   d_sel[E * CAP];
__device__ int   d_valid[E * CAP];
__device__ int   d_idx[T * 2];
__device__ float d_wts[T * 2];
__device__ __align__(16) __nv_bfloat16 d_xin_bf[(size_t)E * CAP * K1];
__device__ __align__(16) __nv_bfloat16 d_wgu_bf[(size_t)E * NB1 * K1];
__device__ __align__(16) __nv_bfloat16 d_wd_bf [(size_t)E * NB2 * K2];
__device__ __align__(16) __nv_bfloat16 d_act_bf[(size_t)E * CAP * K2];
__device__ float d_eout[(size_t)E * CAP * H];

// ---------------------------------------------------------------------------
// PTX helpers
// ---------------------------------------------------------------------------
__device__ __forceinline__ uint32_t smem_u32(const void* p) {
    uint32_t a;
    asm("{ .reg .u64 t; cvta.to.shared.u64 t, %1; cvt.u32.u64 %0, t; }" : "=r"(a) : "l"(p));
    return a;
}
#define CP_ASYNC16(dst, src) \
    asm volatile("cp.async.cg.shared.global [%0], [%1], 16;" :: "r"(dst), "l"(src))
#define CP_COMMIT() asm volatile("cp.async.commit_group;" ::: "memory")
#define CP_WAIT3()  asm volatile("cp.async.wait_group 3;" ::: "memory")

__device__ __forceinline__ void ldmx4(uint32_t& r0, uint32_t& r1, uint32_t& r2,
                                      uint32_t& r3, uint32_t a) {
    asm volatile("ldmatrix.sync.aligned.m8n8.x4.shared.b16 {%0,%1,%2,%3}, [%4];"
                 : "=r"(r0), "=r"(r1), "=r"(r2), "=r"(r3) : "r"(a));
}
__device__ __forceinline__ void mma_bf16(float* c, uint32_t a0, uint32_t a1,
                                         uint32_t a2, uint32_t a3,
                                         uint32_t b0, uint32_t b1) {
    asm volatile(
        "mma.sync.aligned.m16n8k16.row.col.f32.bf16.bf16.f32 "
        "{%0,%1,%2,%3}, {%4,%5,%6,%7}, {%8,%9}, {%0,%1,%2,%3};"
        : "+f"(c[0]), "+f"(c[1]), "+f"(c[2]), "+f"(c[3])
        : "r"(a0), "r"(a1), "r"(a2), "r"(a3), "r"(b0), "r"(b1));
}

// ---------------------------------------------------------------------------
// Kernel A: LayerNorm + router + top-2 (one block / token)
// ---------------------------------------------------------------------------
__global__ void __launch_bounds__(256) ln_router_kernel(
    const float* __restrict__ x, const float* __restrict__ rw,
    const float* __restrict__ gamma, const float* __restrict__ beta)
{
    int t   = blockIdx.x;
    int tid = threadIdx.x;
    const float4 v = ((const float4*)(x + (size_t)t * H))[tid];

    __shared__ float sdata[256];
    float s = v.x + v.y + v.z + v.w;
    sdata[tid] = s; __syncthreads();
    #pragma unroll
    for (int o = 128; o > 0; o >>= 1) { if (tid < o) sdata[tid] += sdata[tid + o]; __syncthreads(); }
    float mu = sdata[0] * (1.0f / H);
    __syncthreads();

    float dx0 = v.x - mu, dx1 = v.y - mu, dx2 = v.z - mu, dx3 = v.w - mu;
    s = dx0 * dx0 + dx1 * dx1 + dx2 * dx2 + dx3 * dx3;
    sdata[tid] = s; __syncthreads();
    #pragma unroll
    for (int o = 128; o > 0; o >>= 1) { if (tid < o) sdata[tid] += sdata[tid + o]; __syncthreads(); }
    float rstd = rsqrtf(sdata[0] * (1.0f / H) + 1e-5f);
    __syncthreads();

    float4 g4 = ((const float4*)gamma)[tid];
    float4 b4 = ((const float4*)beta)[tid];
    float tl[4];
    tl[0] = dx0 * rstd * g4.x + b4.x;
    tl[1] = dx1 * rstd * g4.y + b4.y;
    tl[2] = dx2 * rstd * g4.z + b4.z;
    tl[3] = dx3 * rstd * g4.w + b4.w;
    ((float4*)(d_tokens_ln + (size_t)t * H))[tid] = make_float4(tl[0], tl[1], tl[2], tl[3]);

    int h0 = tid * 4;
    float acc[E];
    #pragma unroll
    for (int e = 0; e < E; e++) acc[e] = 0.0f;
    #pragma unroll
    for (int j = 0; j < 4; j++) {
        const float* rwr = rw + (size_t)(h0 + j) * E;
        #pragma unroll
        for (int e = 0; e < E; e++) acc[e] += tl[j] * rwr[e];
    }
    #pragma unroll
    for (int off = 16; off > 0; off >>= 1)
        #pragma unroll
        for (int e = 0; e < E; e++)
            acc[e] += __shfl_down_sync(0xffffffffu, acc[e], off);

    __shared__ float wlog[8][E];
    int warp = tid >> 5, lane = tid & 31;
    if (lane == 0)
        #pragma unroll
        for (int e = 0; e < E; e++) wlog[warp][e] = acc[e];
    __syncthreads();

    if (tid == 0) {
        float lg[E];
        #pragma unroll
        for (int e = 0; e < E; e++) {
            float sv = 0.0f;
            #pragma unroll
            for (int w = 0; w < 8; w++) sv += wlog[w][e];
            lg[e] = sv;
        }
        float mx = lg[0];
        #pragma unroll
        for (int e = 1; e < E; e++) mx = fmaxf(mx, lg[e]);
        float p[E];
        #pragma unroll
        for (int e = 0; e < E; e++) p[e] = expf(lg[e] - mx);
        int i0 = 0; float b0 = p[0];
        #pragma unroll
        for (int e = 1; e < E; e++) if (p[e] > b0) { b0 = p[e]; i0 = e; }
        int i1 = -1; float b1 = -1.0f;
        #pragma unroll
        for (int e = 0; e < E; e++) if (e != i0 && p[e] > b1) { b1 = p[e]; i1 = e; }
        float inv = 1.0f / (b0 + b1);
        d_idx[2 * t] = i0; d_idx[2 * t + 1] = i1;
        d_wts[2 * t] = b0 * inv; d_wts[2 * t + 1] = b1 * inv;
    }
}

// ---------------------------------------------------------------------------
// Kernel B: capacity assignment (stable), one block / expert
// ---------------------------------------------------------------------------
__global__ void __launch_bounds__(1024) assign_kernel()
{
    int e = blockIdx.x, tid = threadIdx.x;
    int lane = tid & 31, warp = tid >> 5;
    __shared__ int warpCnt[32];
    __shared__ int s_totalSel, s_runSel, s_runUnsel, s_chunkSel;

    int cnt = 0;
    for (int t = tid; t < T; t += 1024)
        cnt += (d_idx[2 * t] == e) | (d_idx[2 * t + 1] == e);
    #pragma unroll
    for (int off = 16; off > 0; off >>= 1) cnt += __shfl_down_sync(0xffffffffu, cnt, off);
    if (lane == 0) warpCnt[warp] = cnt;
    __syncthreads();
    if (tid == 0) {
        int sv = 0;
        for (int w = 0; w < 32; w++) sv += warpCnt[w];
        s_totalSel = sv; s_runSel = 0; s_runUnsel = 0;
    }
    __syncthreads();
    int totalSel = s_totalSel;

    for (int base = 0; base < T; base += 1024) {
        int t = base + tid;
        int m = (d_idx[2 * t] == e) | (d_idx[2 * t + 1] == e);
        unsigned bal = __ballot_sync(0xffffffffu, m);
        int wpre = __popc(bal & ((1u << lane) - 1u));
        if (lane == 0) warpCnt[warp] = __popc(bal);
        __syncthreads();
        if (tid == 0) {
            int sv = 0;
            for (int w = 0; w < 32; w++) { int c = warpCnt[w]; warpCnt[w] = sv; sv += c; }
            s_chunkSel = sv;
        }
        __syncthreads();
        int selPre = warpCnt[warp] + wpre;
        int rs = s_runSel, ru = s_runUnsel;
        int pos = m ? (rs + selPre) : (totalSel + ru + (tid - selPre));
        if (pos < CAP) { d_sel[e * CAP + pos] = t; d_valid[e * CAP + pos] = m; }
        __syncthreads();
        if (tid == 0) { s_runSel = rs + s_chunkSel; s_runUnsel = ru + (1024 - s_chunkSel); }
        __syncthreads();
    }
}

// ---------------------------------------------------------------------------
// Kernel C: gather + triple-split convert: xin_bf[ec][3h] = (hi,hi,lo)
// ---------------------------------------------------------------------------
__global__ void __launch_bounds__(128) gather_convert_kernel()
{
    int ec = blockIdx.x, tid = threadIdx.x;
    int v = d_valid[ec], s = d_sel[ec];
    float4 a = make_float4(0.f,0.f,0.f,0.f), b = a;
    if (v) {
        const float4* src = (const float4*)(d_tokens_ln + (size_t)s * H);
        a = src[tid * 2]; b = src[tid * 2 + 1];
    }
    float vv[8] = {a.x, a.y, a.z, a.w, b.x, b.y, b.z, b.w};
    alignas(16) __nv_bfloat16 o[24];
    #pragma unroll
    for (int j = 0; j < 8; j++) {
        __nv_bfloat16 hi = __float2bfloat16(vv[j]);
        __nv_bfloat16 lo = __float2bfloat16(vv[j] - __bfloat162float(hi));
        o[3*j] = hi; o[3*j+1] = hi; o[3*j+2] = lo;
    }
    uint4* dst = (uint4*)(d_xin_bf + (size_t)ec * K1 + tid * 24);
    const uint4* so = (const uint4*)o;
    dst[0] = so[0]; dst[1] = so[1]; dst[2] = so[2];
}

// ---------------------------------------------------------------------------
// Kernel D: gate/up transpose+split [E][H][F]->[E][2F][3H], triple (hi,lo,hi)
// No div/mod in the hot loop: each unit = 8 consecutive k -> 24 bf16.
// ---------------------------------------------------------------------------
__global__ void __launch_bounds__(256) conv_gateup_kernel(
    const float* __restrict__ wg, const float* __restrict__ wu)
{
    int f0 = blockIdx.x * 32, h0 = blockIdx.y * 64, e = blockIdx.z;
    __shared__ float sg[32][65], su[32][65];
    int t = threadIdx.x, fi = t & 31, hr = t >> 5;
    #pragma unroll
    for (int it = 0; it < 8; it++) {
        int hl = hr + it * 8;
        size_t base = ((size_t)e * H + h0 + hl) * F + f0 + fi;
        sg[fi][hl] = wg[base];
        su[fi][hl] = wu[base];
    }
    __syncthreads();
    #pragma unroll
    for (int it = 0; it < 2; it++) {                 // 64 rows * 8 units / 256
        int u = t + it * 256;
        int r = u >> 3, unit = u & 7;
        int fl = r >> 1, sfl = r & 1;
        const float (*sm)[65] = sfl ? su : sg;
        alignas(16) __nv_bfloat16 o[24];
        #pragma unroll
        for (int j = 0; j < 8; j++) {
            float v = sm[fl][unit * 8 + j];
            __nv_bfloat16 hi = __float2bfloat16(v);
            __nv_bfloat16 lo = __float2bfloat16(v - __bfloat162float(hi));
            o[3*j] = hi; o[3*j+1] = lo; o[3*j+2] = hi;
        }
        uint4* dst = (uint4*)(d_wgu_bf + ((size_t)e * NB1 + 2 * f0 + r) * K1
                              + 3 * h0 + unit * 24);
        const uint4* so = (const uint4*)o;
        dst[0] = so[0]; dst[1] = so[1]; dst[2] = so[2];
    }
}

// ---------------------------------------------------------------------------
// Kernel E: down transpose+split [E][F][H]->[E][H][3F], triple (hi,lo,hi)
// ---------------------------------------------------------------------------
__global__ void __launch_bounds__(256) conv_down_kernel(const float* __restrict__ wd)
{
    int f0 = blockIdx.x * 64, h0 = blockIdx.y * 32, e = blockIdx.z;
    __shared__ float sd[32][65];
    int t = threadIdx.x, hl = t & 31, fr = t >> 5;
    #pragma unroll
    for (int it = 0; it < 8; it++) {
        int fl = fr + it * 8;
        sd[hl][fl] = wd[((size_t)e * F + f0 + fl) * H + h0 + hl];
    }
    __syncthreads();
    {                                                // 32 rows * 8 units = 256
        int r = t >> 3, unit = t & 7;
        alignas(16) __nv_bfloat16 o[24];
        #pragma unroll
        for (int j = 0; j < 8; j++) {
            float v = sd[r][unit * 8 + j];
            __nv_bfloat16 hi = __float2bfloat16(v);
            __nv_bfloat16 lo = __float2bfloat16(v - __bfloat162float(hi));
            o[3*j] = hi; o[3*j+1] = lo; o[3*j+2] = hi;
        }
        uint4* dst = (uint4*)(d_wd_bf + ((size_t)e * NB2 + h0 + r) * K2
                              + 3 * f0 + unit * 24);
        const uint4* so = (const uint4*)o;
        dst[0] = so[0]; dst[1] = so[1]; dst[2] = so[2];
    }
}

// ---------------------------------------------------------------------------
// mma.sync bf16 GEMM: 128x128 CTA tile, BK=32, 8 warps, 4-stage cp.async.
// Grid: (m-tiles, n-tiles, E) — m fastest so B n-slices stay hot in L2.
// GATEUP epilogue: silu(g)*u -> triple-split -> smem stage -> coalesced STG.
// ---------------------------------------------------------------------------
constexpr int STAGE_BYTES = 20480;            // A 128*80 + B 128*80
constexpr int GEMM_SMEM   = 4 * STAGE_BYTES;  // 81920

template<int KT, int NB, bool GATEUP>
__global__ void __launch_bounds__(256, 2) moe_gemm_kernel()
{
    constexpr int NC = KT / 32;
    extern __shared__ char smem_raw[];
    uint32_t sb = smem_u32(smem_raw);
    int tid = threadIdx.x, wid = tid >> 5, lane = tid & 31;
    int e = blockIdx.z, m0 = blockIdx.x * 128, n0 = blockIdx.y * 128;
    int wm0 = (wid & 3) * 32, wn0 = (wid >> 2) * 64;

    const __nv_bfloat16* Arow =
        (GATEUP ? d_xin_bf : d_act_bf) + ((size_t)e * CAP + m0) * KT;
    const __nv_bfloat16* Brow =
        (GATEUP ? d_wgu_bf : d_wd_bf) + ((size_t)e * NB + n0) * KT;

    float acc[2][8][4] = {};

    auto loadst = [&](int s, int chunk) {
        uint32_t abase = sb + s * STAGE_BYTES;
        uint32_t bbase = abase + 10240;
        const char* ag = (const char*)Arow + chunk * 64;
        const char* bg = (const char*)Brow + chunk * 64;
        #pragma unroll
        for (int it = 0; it < 2; it++) {
            int u = tid + it * 256; int row = u >> 2, c = u & 3;
            CP_ASYNC16(abase + row * 80 + c * 16, ag + (size_t)row * (KT * 2) + c * 16);
        }
        #pragma unroll
        for (int it = 0; it < 2; it++) {
            int u = tid + it * 256; int row = u >> 2, c = u & 3;
            CP_ASYNC16(bbase + row * 80 + c * 16, bg + (size_t)row * (KT * 2) + c * 16);
        }
        CP_COMMIT();
    };

    #pragma unroll
    for (int s = 0; s < 4; s++) loadst(s, s);

    for (int i = 0; i < NC; i++) {
        int s = i & 3;
        CP_WAIT3();
        __syncthreads();
        uint32_t abase = sb + s * STAGE_BYTES;
        uint32_t bbase = abase + 10240;
        #pragma unroll
        for (int kk = 0; kk < 2; kk++) {
            uint32_t a[2][4];
            #pragma unroll
            for (int ms = 0; ms < 2; ms++) {
                uint32_t ad = abase + (wm0 + ms * 16 + (lane & 15)) * 80
                            + (kk * 2 + (lane >> 4)) * 16;
                ldmx4(a[ms][0], a[ms][1], a[ms][2], a[ms][3], ad);
            }
            #pragma unroll
            for (int np = 0; np < 4; np++) {
                uint32_t b0, b1, b2, b3;
                uint32_t bd = bbase + (wn0 + np * 16 + (lane & 7) + ((lane >> 4) << 3)) * 80
                            + (kk * 2 + ((lane >> 3) & 1)) * 16;
                ldmx4(b0, b1, b2, b3, bd);
                #pragma unroll
                for (int ms = 0; ms < 2; ms++) {
                    mma_bf16(acc[ms][np * 2],     a[ms][0], a[ms][1], a[ms][2], a[ms][3], b0, b1);
                    mma_bf16(acc[ms][np * 2 + 1], a[ms][0], a[ms][1], a[ms][2], a[ms][3], b2, b3);
                }
            }
        }
        __syncthreads();
        if (i + 4 < NC) loadst(s, i + 4); else CP_COMMIT();
    }

    // -------- epilogue --------
    if (GATEUP) {
        // stage triple-split act rows in smem, then coalesced 16B stores
        __syncthreads();
        __nv_bfloat16* sact = (__nv_bfloat16*)smem_raw;   // 128 rows x 192 bf16
        #pragma unroll
        for (int ms = 0; ms < 2; ms++) {
            #pragma unroll
            for (int np = 0; np < 8; np++) {
                int f_l = (wn0 >> 1) + (np >> 1) * 8 + (np & 1) * 4 + (lane & 3);
                // careful: np indexes acc pairs over n: nc = wn0 + np*8 + (lane&3)*2
                // f_l = nc/2 = wn0/2 + np*4 + (lane&3)  (nc even)
                f_l = (wn0 >> 1) + np * 4 + (lane & 3);
                #pragma unroll
                for (int h = 0; h < 2; h++) {
                    int row_l = wm0 + ms * 16 + (lane >> 2) + h * 8;
                    float g  = acc[ms][np][2 * h];
                    float uu = acc[ms][np][2 * h + 1];
                    float av = (g / (1.0f + __expf(-g))) * uu;
                    __nv_bfloat16 hi = __float2bfloat16(av);
                    __nv_bfloat16 lo = __float2bfloat16(av - __bfloat162float(hi));
                    int o = row_l * 192 + f_l * 3;
                    sact[o] = hi; sact[o + 1] = hi; sact[o + 2] = lo;
                }
            }
        }
        __syncthreads();
        int row = tid >> 1, half = tid & 1;
        const uint4* src = (const uint4*)(sact + row * 192) + half * 12;
        uint4* dst = (uint4*)(d_act_bf + ((size_t)e * CAP + m0 + row) * K2
                              + 3 * (n0 >> 1)) + half * 12;
        #pragma unroll
        for (int q = 0; q < 12; q++) dst[q] = src[q];
    } else {
        #pragma unroll
        for (int ms = 0; ms < 2; ms++) {
            #pragma unroll
            for (int np = 0; np < 8; np++) {
                int r0 = m0 + wm0 + ms * 16 + (lane >> 2);
                int nc = n0 + wn0 + np * 8 + (lane & 3) * 2;
                #pragma unroll
                for (int h = 0; h < 2; h++) {
                    int row = r0 + h * 8;
                    float2* p = (float2*)(d_eout + ((size_t)e * CAP + row) * H + nc);
                    *p = make_float2(acc[ms][np][2 * h], acc[ms][np][2 * h + 1]);
                }
            }
        }
    }
}

// ---------------------------------------------------------------------------
// Kernel F: combine
// ---------------------------------------------------------------------------
__global__ void __launch_bounds__(256) combine_kernel(
    const float* __restrict__ x, float* __restrict__ out)
{
    int i = blockIdx.x * 256 + threadIdx.x;
    int h4 = i & (H / 4 - 1);
    int t  = i >> 8;
    int slot = min(t, CAP - 1);
    int i0 = d_idx[2 * t], i1 = d_idx[2 * t + 1];
    float w0 = d_wts[2 * t], w1 = d_wts[2 * t + 1];
    const float4* e4 = (const float4*)d_eout;
    float4 a  = ((const float4*)x)[i];
    float4 g0 = e4[((size_t)i0 * CAP + slot) * (H / 4) + h4];
    float4 g1 = e4[((size_t)i1 * CAP + slot) * (H / 4) + h4];
    float4 o;
    o.x = a.x + w0 * g0.x + w1 * g1.x;
    o.y = a.y + w0 * g0.y + w1 * g1.y;
    o.z = a.z + w0 * g0.z + w1 * g1.z;
    o.w = a.w + w0 * g0.w + w1 * g1.w;
    ((float4*)out)[i] = o;
}

// ---------------------------------------------------------------------------
// Launch
// ---------------------------------------------------------------------------
extern "C" void kernel_launch(void* const* d_in, const int* in_sizes, int n_in,
                              void* d_out, int out_size)
{
    const float* x     = (const float*)d_in[0];
    const float* rw    = (const float*)d_in[1];
    const float* wg    = (const float*)d_in[2];
    const float* wu    = (const float*)d_in[3];
    const float* wd    = (const float*)d_in[4];
    const float* gamma = (const float*)d_in[5];
    const float* beta  = (const float*)d_in[6];
    float*       out   = (float*)d_out;

    cudaFuncSetAttribute(moe_gemm_kernel<K1, NB1, true>,
                         cudaFuncAttributeMaxDynamicSharedMemorySize, GEMM_SMEM);
    cudaFuncSetAttribute(moe_gemm_kernel<K2, NB2, false>,
                         cudaFuncAttributeMaxDynamicSharedMemorySize, GEMM_SMEM);

    ln_router_kernel<<<T, 256>>>(x, rw, gamma, beta);
    assign_kernel<<<E, 1024>>>();
    conv_gateup_kernel<<<dim3(F / 32, H / 64, E), 256>>>(wg, wu);
    conv_down_kernel<<<dim3(F / 64, H / 32, E), 256>>>(wd);
    gather_convert_kernel<<<E * CAP, 128>>>();
    moe_gemm_kernel<K1, NB1, true ><<<dim3(CAP / 128, NB1 / 128, E), 256, GEMM_SMEM>>>();
    moe_gemm_kernel<K2, NB2, false><<<dim3(CAP / 128, NB2 / 128, E), 256, GEMM_SMEM>>>();
    combine_kernel<<<(T * H / 4) / 256, 256>>>(x, out);
}

// round 5
// speedup vs baseline: 3.1390x; 1.3692x over previous
#include <cuda_runtime.h>
#include <cuda_bf16.h>
#include <cuda_fp16.h>
#include <cstdint>

// ---------------------------------------------------------------------------
// Problem constants
// ---------------------------------------------------------------------------
constexpr int T   = 4096;
constexpr int H   = 1024;
constexpr int F   = 2048;
constexpr int E   = 8;
constexpr int CAP = 640;

constexpr int K1  = 2 * H;   // 2048  (fp16 pair-split K for GEMM1)
constexpr int K2  = 2 * F;   // 4096  (fp16 pair-split K for GEMM2)
constexpr int NB1 = 2 * F;   // 4096  interleaved gate/up rows
constexpr int NB2 = H;       // 1024

// ---------------------------------------------------------------------------
// Scratch
// ---------------------------------------------------------------------------
__device__ float d_tokens_ln[(size_t)T * H];
__device__ int   d_sel[E * CAP];
__device__ int   d_valid[E * CAP];
__device__ int   d_idx[T * 2];
__device__ float d_wts[T * 2];
__device__ __align__(16) __half d_xin_fp[(size_t)E * CAP * K1];   // A1: (hi,lo)
__device__ __align__(16) __half d_wgu_fp[(size_t)E * NB1 * K1];   // B1: (hi,hi)
__device__ __align__(16) __half d_wd_fp [(size_t)E * NB2 * K2];   // B2: (hi,hi)
__device__ __align__(16) __half d_act_fp[(size_t)E * CAP * K2];   // A2: (hi,lo)
__device__ float d_eout[(size_t)E * CAP * H];

// ---------------------------------------------------------------------------
// PTX helpers
// ---------------------------------------------------------------------------
__device__ __forceinline__ uint32_t smem_u32(const void* p) {
    uint32_t a;
    asm("{ .reg .u64 t; cvta.to.shared.u64 t, %1; cvt.u32.u64 %0, t; }" : "=r"(a) : "l"(p));
    return a;
}
#define CP_ASYNC16(dst, src) \
    asm volatile("cp.async.cg.shared.global [%0], [%1], 16;" :: "r"(dst), "l"(src))
#define CP_COMMIT() asm volatile("cp.async.commit_group;" ::: "memory")
#define CP_WAIT3()  asm volatile("cp.async.wait_group 3;" ::: "memory")

__device__ __forceinline__ void ldmx4(uint32_t& r0, uint32_t& r1, uint32_t& r2,
                                      uint32_t& r3, uint32_t a) {
    asm volatile("ldmatrix.sync.aligned.m8n8.x4.shared.b16 {%0,%1,%2,%3}, [%4];"
                 : "=r"(r0), "=r"(r1), "=r"(r2), "=r"(r3) : "r"(a));
}
__device__ __forceinline__ void mma_f16(float* c, uint32_t a0, uint32_t a1,
                                        uint32_t a2, uint32_t a3,
                                        uint32_t b0, uint32_t b1) {
    asm volatile(
        "mma.sync.aligned.m16n8k16.row.col.f32.f16.f16.f32 "
        "{%0,%1,%2,%3}, {%4,%5,%6,%7}, {%8,%9}, {%0,%1,%2,%3};"
        : "+f"(c[0]), "+f"(c[1]), "+f"(c[2]), "+f"(c[3])
        : "r"(a0), "r"(a1), "r"(a2), "r"(a3), "r"(b0), "r"(b1));
}

// ---------------------------------------------------------------------------
// Kernel A: LayerNorm + router + top-2 (one block / token)
// ---------------------------------------------------------------------------
__global__ void __launch_bounds__(256) ln_router_kernel(
    const float* __restrict__ x, const float* __restrict__ rw,
    const float* __restrict__ gamma, const float* __restrict__ beta)
{
    int t   = blockIdx.x;
    int tid = threadIdx.x;
    const float4 v = ((const float4*)(x + (size_t)t * H))[tid];

    __shared__ float sdata[256];
    float s = v.x + v.y + v.z + v.w;
    sdata[tid] = s; __syncthreads();
    #pragma unroll
    for (int o = 128; o > 0; o >>= 1) { if (tid < o) sdata[tid] += sdata[tid + o]; __syncthreads(); }
    float mu = sdata[0] * (1.0f / H);
    __syncthreads();

    float dx0 = v.x - mu, dx1 = v.y - mu, dx2 = v.z - mu, dx3 = v.w - mu;
    s = dx0 * dx0 + dx1 * dx1 + dx2 * dx2 + dx3 * dx3;
    sdata[tid] = s; __syncthreads();
    #pragma unroll
    for (int o = 128; o > 0; o >>= 1) { if (tid < o) sdata[tid] += sdata[tid + o]; __syncthreads(); }
    float rstd = rsqrtf(sdata[0] * (1.0f / H) + 1e-5f);
    __syncthreads();

    float4 g4 = ((const float4*)gamma)[tid];
    float4 b4 = ((const float4*)beta)[tid];
    float tl[4];
    tl[0] = dx0 * rstd * g4.x + b4.x;
    tl[1] = dx1 * rstd * g4.y + b4.y;
    tl[2] = dx2 * rstd * g4.z + b4.z;
    tl[3] = dx3 * rstd * g4.w + b4.w;
    ((float4*)(d_tokens_ln + (size_t)t * H))[tid] = make_float4(tl[0], tl[1], tl[2], tl[3]);

    int h0 = tid * 4;
    float acc[E];
    #pragma unroll
    for (int e = 0; e < E; e++) acc[e] = 0.0f;
    #pragma unroll
    for (int j = 0; j < 4; j++) {
        const float* rwr = rw + (size_t)(h0 + j) * E;
        #pragma unroll
        for (int e = 0; e < E; e++) acc[e] += tl[j] * rwr[e];
    }
    #pragma unroll
    for (int off = 16; off > 0; off >>= 1)
        #pragma unroll
        for (int e = 0; e < E; e++)
            acc[e] += __shfl_down_sync(0xffffffffu, acc[e], off);

    __shared__ float wlog[8][E];
    int warp = tid >> 5, lane = tid & 31;
    if (lane == 0)
        #pragma unroll
        for (int e = 0; e < E; e++) wlog[warp][e] = acc[e];
    __syncthreads();

    if (tid == 0) {
        float lg[E];
        #pragma unroll
        for (int e = 0; e < E; e++) {
            float sv = 0.0f;
            #pragma unroll
            for (int w = 0; w < 8; w++) sv += wlog[w][e];
            lg[e] = sv;
        }
        float mx = lg[0];
        #pragma unroll
        for (int e = 1; e < E; e++) mx = fmaxf(mx, lg[e]);
        float p[E];
        #pragma unroll
        for (int e = 0; e < E; e++) p[e] = expf(lg[e] - mx);
        int i0 = 0; float b0 = p[0];
        #pragma unroll
        for (int e = 1; e < E; e++) if (p[e] > b0) { b0 = p[e]; i0 = e; }
        int i1 = -1; float b1 = -1.0f;
        #pragma unroll
        for (int e = 0; e < E; e++) if (e != i0 && p[e] > b1) { b1 = p[e]; i1 = e; }
        float inv = 1.0f / (b0 + b1);
        d_idx[2 * t] = i0; d_idx[2 * t + 1] = i1;
        d_wts[2 * t] = b0 * inv; d_wts[2 * t + 1] = b1 * inv;
    }
}

// ---------------------------------------------------------------------------
// Kernel B: capacity assignment (stable), one block / expert
// ---------------------------------------------------------------------------
__global__ void __launch_bounds__(1024) assign_kernel()
{
    int e = blockIdx.x, tid = threadIdx.x;
    int lane = tid & 31, warp = tid >> 5;
    __shared__ int warpCnt[32];
    __shared__ int s_totalSel, s_runSel, s_runUnsel, s_chunkSel;

    int cnt = 0;
    for (int t = tid; t < T; t += 1024)
        cnt += (d_idx[2 * t] == e) | (d_idx[2 * t + 1] == e);
    #pragma unroll
    for (int off = 16; off > 0; off >>= 1) cnt += __shfl_down_sync(0xffffffffu, cnt, off);
    if (lane == 0) warpCnt[warp] = cnt;
    __syncthreads();
    if (tid == 0) {
        int sv = 0;
        for (int w = 0; w < 32; w++) sv += warpCnt[w];
        s_totalSel = sv; s_runSel = 0; s_runUnsel = 0;
    }
    __syncthreads();
    int totalSel = s_totalSel;

    for (int base = 0; base < T; base += 1024) {
        int t = base + tid;
        int m = (d_idx[2 * t] == e) | (d_idx[2 * t + 1] == e);
        unsigned bal = __ballot_sync(0xffffffffu, m);
        int wpre = __popc(bal & ((1u << lane) - 1u));
        if (lane == 0) warpCnt[warp] = __popc(bal);
        __syncthreads();
        if (tid == 0) {
            int sv = 0;
            for (int w = 0; w < 32; w++) { int c = warpCnt[w]; warpCnt[w] = sv; sv += c; }
            s_chunkSel = sv;
        }
        __syncthreads();
        int selPre = warpCnt[warp] + wpre;
        int rs = s_runSel, ru = s_runUnsel;
        int pos = m ? (rs + selPre) : (totalSel + ru + (tid - selPre));
        if (pos < CAP) { d_sel[e * CAP + pos] = t; d_valid[e * CAP + pos] = m; }
        __syncthreads();
        if (tid == 0) { s_runSel = rs + s_chunkSel; s_runUnsel = ru + (1024 - s_chunkSel); }
        __syncthreads();
    }
}

// ---------------------------------------------------------------------------
// Kernel C: gather + pair-split: xin_fp[ec][2h] = (hi, lo)
// ---------------------------------------------------------------------------
__global__ void __launch_bounds__(128) gather_convert_kernel()
{
    int ec = blockIdx.x, tid = threadIdx.x;
    int v = d_valid[ec], s = d_sel[ec];
    float4 a = make_float4(0.f,0.f,0.f,0.f), b = a;
    if (v) {
        const float4* src = (const float4*)(d_tokens_ln + (size_t)s * H);
        a = src[tid * 2]; b = src[tid * 2 + 1];
    }
    float vv[8] = {a.x, a.y, a.z, a.w, b.x, b.y, b.z, b.w};
    alignas(16) __half o[16];
    #pragma unroll
    for (int j = 0; j < 8; j++) {
        __half hi = __float2half(vv[j]);
        o[2*j]   = hi;
        o[2*j+1] = __float2half(vv[j] - __half2float(hi));
    }
    uint4* dst = (uint4*)(d_xin_fp + (size_t)ec * K1 + tid * 16);
    const uint4* so = (const uint4*)o;
    dst[0] = so[0]; dst[1] = so[1];
}

// ---------------------------------------------------------------------------
// Kernel D: gate/up transpose+dup [E][H][F] -> [E][2F][2H], pair (hi, hi)
// ---------------------------------------------------------------------------
__global__ void __launch_bounds__(256) conv_gateup_kernel(
    const float* __restrict__ wg, const float* __restrict__ wu)
{
    int f0 = blockIdx.x * 32, h0 = blockIdx.y * 64, e = blockIdx.z;
    __shared__ float sg[32][65], su[32][65];
    int t = threadIdx.x, fi = t & 31, hr = t >> 5;
    #pragma unroll
    for (int it = 0; it < 8; it++) {
        int hl = hr + it * 8;
        size_t base = ((size_t)e * H + h0 + hl) * F + f0 + fi;
        sg[fi][hl] = wg[base];
        su[fi][hl] = wu[base];
    }
    __syncthreads();
    #pragma unroll
    for (int it = 0; it < 2; it++) {                 // 64 rows * 8 units / 256
        int u = t + it * 256;
        int r = u >> 3, unit = u & 7;
        int fl = r >> 1, sfl = r & 1;
        const float (*sm)[65] = sfl ? su : sg;
        alignas(16) __half o[16];
        #pragma unroll
        for (int j = 0; j < 8; j++) {
            __half hi = __float2half(sm[fl][unit * 8 + j]);
            o[2*j] = hi; o[2*j+1] = hi;
        }
        uint4* dst = (uint4*)(d_wgu_fp + ((size_t)e * NB1 + 2 * f0 + r) * K1
                              + 2 * h0 + unit * 16);
        const uint4* so = (const uint4*)o;
        dst[0] = so[0]; dst[1] = so[1];
    }
}

// ---------------------------------------------------------------------------
// Kernel E: down transpose+dup [E][F][H] -> [E][H][2F], pair (hi, hi)
// ---------------------------------------------------------------------------
__global__ void __launch_bounds__(256) conv_down_kernel(const float* __restrict__ wd)
{
    int f0 = blockIdx.x * 64, h0 = blockIdx.y * 32, e = blockIdx.z;
    __shared__ float sd[32][65];
    int t = threadIdx.x, hl = t & 31, fr = t >> 5;
    #pragma unroll
    for (int it = 0; it < 8; it++) {
        int fl = fr + it * 8;
        sd[hl][fl] = wd[((size_t)e * F + f0 + fl) * H + h0 + hl];
    }
    __syncthreads();
    {                                                // 32 rows * 8 units = 256
        int r = t >> 3, unit = t & 7;
        alignas(16) __half o[16];
        #pragma unroll
        for (int j = 0; j < 8; j++) {
            __half hi = __float2half(sd[r][unit * 8 + j]);
            o[2*j] = hi; o[2*j+1] = hi;
        }
        uint4* dst = (uint4*)(d_wd_fp + ((size_t)e * NB2 + h0 + r) * K2
                              + 2 * f0 + unit * 16);
        const uint4* so = (const uint4*)o;
        dst[0] = so[0]; dst[1] = so[1];
    }
}

// ---------------------------------------------------------------------------
// mma.sync fp16 GEMM: 128x128 CTA tile, BK=32, 8 warps, 4-stage cp.async.
// Grid: (m-tiles, n-tiles, E) — m fastest so B n-slices stay hot in L2.
// GATEUP epilogue: silu(g)*u -> (hi,lo) pair -> smem stage -> coalesced STG.
// ---------------------------------------------------------------------------
constexpr int STAGE_BYTES = 20480;            // A 128*80 + B 128*80
constexpr int GEMM_SMEM   = 4 * STAGE_BYTES;  // 81920

template<int KT, int NB, bool GATEUP>
__global__ void __launch_bounds__(256, 2) moe_gemm_kernel()
{
    constexpr int NC = KT / 32;
    extern __shared__ char smem_raw[];
    uint32_t sb = smem_u32(smem_raw);
    int tid = threadIdx.x, wid = tid >> 5, lane = tid & 31;
    int e = blockIdx.z, m0 = blockIdx.x * 128, n0 = blockIdx.y * 128;
    int wm0 = (wid & 3) * 32, wn0 = (wid >> 2) * 64;

    const __half* Arow =
        (GATEUP ? d_xin_fp : d_act_fp) + ((size_t)e * CAP + m0) * KT;
    const __half* Brow =
        (GATEUP ? d_wgu_fp : d_wd_fp) + ((size_t)e * NB + n0) * KT;

    float acc[2][8][4] = {};

    auto loadst = [&](int s, int chunk) {
        uint32_t abase = sb + s * STAGE_BYTES;
        uint32_t bbase = abase + 10240;
        const char* ag = (const char*)Arow + chunk * 64;
        const char* bg = (const char*)Brow + chunk * 64;
        #pragma unroll
        for (int it = 0; it < 2; it++) {
            int u = tid + it * 256; int row = u >> 2, c = u & 3;
            CP_ASYNC16(abase + row * 80 + c * 16, ag + (size_t)row * (KT * 2) + c * 16);
        }
        #pragma unroll
        for (int it = 0; it < 2; it++) {
            int u = tid + it * 256; int row = u >> 2, c = u & 3;
            CP_ASYNC16(bbase + row * 80 + c * 16, bg + (size_t)row * (KT * 2) + c * 16);
        }
        CP_COMMIT();
    };

    #pragma unroll
    for (int s = 0; s < 4; s++) loadst(s, s);

    for (int i = 0; i < NC; i++) {
        int s = i & 3;
        CP_WAIT3();
        __syncthreads();
        uint32_t abase = sb + s * STAGE_BYTES;
        uint32_t bbase = abase + 10240;
        #pragma unroll
        for (int kk = 0; kk < 2; kk++) {
            uint32_t a[2][4];
            #pragma unroll
            for (int ms = 0; ms < 2; ms++) {
                uint32_t ad = abase + (wm0 + ms * 16 + (lane & 15)) * 80
                            + (kk * 2 + (lane >> 4)) * 16;
                ldmx4(a[ms][0], a[ms][1], a[ms][2], a[ms][3], ad);
            }
            #pragma unroll
            for (int np = 0; np < 4; np++) {
                uint32_t b0, b1, b2, b3;
                uint32_t bd = bbase + (wn0 + np * 16 + (lane & 7) + ((lane >> 4) << 3)) * 80
                            + (kk * 2 + ((lane >> 3) & 1)) * 16;
                ldmx4(b0, b1, b2, b3, bd);
                #pragma unroll
                for (int ms = 0; ms < 2; ms++) {
                    mma_f16(acc[ms][np * 2],     a[ms][0], a[ms][1], a[ms][2], a[ms][3], b0, b1);
                    mma_f16(acc[ms][np * 2 + 1], a[ms][0], a[ms][1], a[ms][2], a[ms][3], b2, b3);
                }
            }
        }
        __syncthreads();
        if (i + 4 < NC) loadst(s, i + 4); else CP_COMMIT();
    }

    // -------- epilogue --------
    if (GATEUP) {
        // silu(g)*u -> fp16 pair (hi,lo) staged in smem, then coalesced STG
        __syncthreads();
        __half* sact = (__half*)smem_raw;            // 128 rows x 128 fp16
        #pragma unroll
        for (int ms = 0; ms < 2; ms++) {
            #pragma unroll
            for (int np = 0; np < 8; np++) {
                int f_l = (wn0 >> 1) + np * 4 + (lane & 3);
                #pragma unroll
                for (int h = 0; h < 2; h++) {
                    int row_l = wm0 + ms * 16 + (lane >> 2) + h * 8;
                    float g  = acc[ms][np][2 * h];
                    float uu = acc[ms][np][2 * h + 1];
                    float av = (g / (1.0f + __expf(-g))) * uu;
                    __half hi = __float2half(av);
                    __half lo = __float2half(av - __half2float(hi));
                    int o = row_l * 128 + f_l * 2;
                    sact[o] = hi; sact[o + 1] = lo;
                }
            }
        }
        __syncthreads();
        int row = tid >> 1, half = tid & 1;
        const uint4* src = (const uint4*)(sact + row * 128) + half * 8;
        uint4* dst = (uint4*)(d_act_fp + ((size_t)e * CAP + m0 + row) * K2 + n0)
                     + half * 8;
        #pragma unroll
        for (int q = 0; q < 8; q++) dst[q] = src[q];
    } else {
        #pragma unroll
        for (int ms = 0; ms < 2; ms++) {
            #pragma unroll
            for (int np = 0; np < 8; np++) {
                int r0 = m0 + wm0 + ms * 16 + (lane >> 2);
                int nc = n0 + wn0 + np * 8 + (lane & 3) * 2;
                #pragma unroll
                for (int h = 0; h < 2; h++) {
                    int row = r0 + h * 8;
                    float2* p = (float2*)(d_eout + ((size_t)e * CAP + row) * H + nc);
                    *p = make_float2(acc[ms][np][2 * h], acc[ms][np][2 * h + 1]);
                }
            }
        }
    }
}

// ---------------------------------------------------------------------------
// Kernel F: combine
// ---------------------------------------------------------------------------
__global__ void __launch_bounds__(256) combine_kernel(
    const float* __restrict__ x, float* __restrict__ out)
{
    int i = blockIdx.x * 256 + threadIdx.x;
    int h4 = i & (H / 4 - 1);
    int t  = i >> 8;
    int slot = min(t, CAP - 1);
    int i0 = d_idx[2 * t], i1 = d_idx[2 * t + 1];
    float w0 = d_wts[2 * t], w1 = d_wts[2 * t + 1];
    const float4* e4 = (const float4*)d_eout;
    float4 a  = ((const float4*)x)[i];
    float4 g0 = e4[((size_t)i0 * CAP + slot) * (H / 4) + h4];
    float4 g1 = e4[((size_t)i1 * CAP + slot) * (H / 4) + h4];
    float4 o;
    o.x = a.x + w0 * g0.x + w1 * g1.x;
    o.y = a.y + w0 * g0.y + w1 * g1.y;
    o.z = a.z + w0 * g0.z + w1 * g1.z;
    o.w = a.w + w0 * g0.w + w1 * g1.w;
    ((float4*)out)[i] = o;
}

// ---------------------------------------------------------------------------
// Launch
// ---------------------------------------------------------------------------
extern "C" void kernel_launch(void* const* d_in, const int* in_sizes, int n_in,
                              void* d_out, int out_size)
{
    const float* x     = (const float*)d_in[0];
    const float* rw    = (const float*)d_in[1];
    const float* wg    = (const float*)d_in[2];
    const float* wu    = (const float*)d_in[3];
    const float* wd    = (const float*)d_in[4];
    const float* gamma = (const float*)d_in[5];
    const float* beta  = (const float*)d_in[6];
    float*       out   = (float*)d_out;

    cudaFuncSetAttribute(moe_gemm_kernel<K1, NB1, true>,
                         cudaFuncAttributeMaxDynamicSharedMemorySize, GEMM_SMEM);
    cudaFuncSetAttribute(moe_gemm_kernel<K2, NB2, false>,
                         cudaFuncAttributeMaxDynamicSharedMemorySize, GEMM_SMEM);

    ln_router_kernel<<<T, 256>>>(x, rw, gamma, beta);
    assign_kernel<<<E, 1024>>>();
    conv_gateup_kernel<<<dim3(F / 32, H / 64, E), 256>>>(wg, wu);
    conv_down_kernel<<<dim3(F / 64, H / 32, E), 256>>>(wd);
    gather_convert_kernel<<<E * CAP, 128>>>();
    moe_gemm_kernel<K1, NB1, true ><<<dim3(CAP / 128, NB1 / 128, E), 256, GEMM_SMEM>>>();
    moe_gemm_kernel<K2, NB2, false><<<dim3(CAP / 128, NB2 / 128, E), 256, GEMM_SMEM>>>();
    combine_kernel<<<(T * H / 4) / 256, 256>>>(x, out);
}

// round 6
// speedup vs baseline: 4.9200x; 1.5674x over previous
#include <cuda_runtime.h>
#include <cuda_bf16.h>
#include <cuda_fp16.h>
#include <cstdint>

// ---------------------------------------------------------------------------
// Problem constants
// ---------------------------------------------------------------------------
constexpr int T   = 4096;
constexpr int H   = 1024;
constexpr int F   = 2048;
constexpr int E   = 8;
constexpr int CAP = 640;

constexpr int KA1 = H;       // 1024  GEMM1 K (pure fp16, no split)
constexpr int KA2 = F;       // 2048  GEMM2 K
constexpr int NB1 = 2 * F;   // 4096  interleaved gate/up rows
constexpr int NB2 = H;       // 1024

// ---------------------------------------------------------------------------
// Scratch
// ---------------------------------------------------------------------------
__device__ float d_tokens_ln[(size_t)T * H];
__device__ int   d_sel[E * CAP];
__device__ int   d_valid[E * CAP];
__device__ int   d_idx[T * 2];
__device__ float d_wts[T * 2];
__device__ __align__(16) __half d_xin_fp[(size_t)E * CAP * KA1];
__device__ __align__(16) __half d_wgu_fp[(size_t)E * NB1 * KA1];
__device__ __align__(16) __half d_wd_fp [(size_t)E * NB2 * KA2];
__device__ __align__(16) __half d_act_fp[(size_t)E * CAP * KA2];
__device__ float d_eout[(size_t)E * CAP * H];

// ---------------------------------------------------------------------------
// PTX helpers
// ---------------------------------------------------------------------------
__device__ __forceinline__ uint32_t smem_u32(const void* p) {
    uint32_t a;
    asm("{ .reg .u64 t; cvta.to.shared.u64 t, %1; cvt.u32.u64 %0, t; }" : "=r"(a) : "l"(p));
    return a;
}
#define CP_ASYNC16(dst, src) \
    asm volatile("cp.async.cg.shared.global [%0], [%1], 16;" :: "r"(dst), "l"(src))
#define CP_COMMIT() asm volatile("cp.async.commit_group;" ::: "memory")
#define CP_WAIT3()  asm volatile("cp.async.wait_group 3;" ::: "memory")

__device__ __forceinline__ void ldmx4(uint32_t& r0, uint32_t& r1, uint32_t& r2,
                                      uint32_t& r3, uint32_t a) {
    asm volatile("ldmatrix.sync.aligned.m8n8.x4.shared.b16 {%0,%1,%2,%3}, [%4];"
                 : "=r"(r0), "=r"(r1), "=r"(r2), "=r"(r3) : "r"(a));
}
__device__ __forceinline__ void mma_f16(float* c, uint32_t a0, uint32_t a1,
                                        uint32_t a2, uint32_t a3,
                                        uint32_t b0, uint32_t b1) {
    asm volatile(
        "mma.sync.aligned.m16n8k16.row.col.f32.f16.f16.f32 "
        "{%0,%1,%2,%3}, {%4,%5,%6,%7}, {%8,%9}, {%0,%1,%2,%3};"
        : "+f"(c[0]), "+f"(c[1]), "+f"(c[2]), "+f"(c[3])
        : "r"(a0), "r"(a1), "r"(a2), "r"(a3), "r"(b0), "r"(b1));
}

// ---------------------------------------------------------------------------
// Kernel A: LayerNorm + router + top-2 (one block / token)
// ---------------------------------------------------------------------------
__global__ void __launch_bounds__(256) ln_router_kernel(
    const float* __restrict__ x, const float* __restrict__ rw,
    const float* __restrict__ gamma, const float* __restrict__ beta)
{
    int t   = blockIdx.x;
    int tid = threadIdx.x;
    const float4 v = ((const float4*)(x + (size_t)t * H))[tid];

    __shared__ float sdata[256];
    float s = v.x + v.y + v.z + v.w;
    sdata[tid] = s; __syncthreads();
    #pragma unroll
    for (int o = 128; o > 0; o >>= 1) { if (tid < o) sdata[tid] += sdata[tid + o]; __syncthreads(); }
    float mu = sdata[0] * (1.0f / H);
    __syncthreads();

    float dx0 = v.x - mu, dx1 = v.y - mu, dx2 = v.z - mu, dx3 = v.w - mu;
    s = dx0 * dx0 + dx1 * dx1 + dx2 * dx2 + dx3 * dx3;
    sdata[tid] = s; __syncthreads();
    #pragma unroll
    for (int o = 128; o > 0; o >>= 1) { if (tid < o) sdata[tid] += sdata[tid + o]; __syncthreads(); }
    float rstd = rsqrtf(sdata[0] * (1.0f / H) + 1e-5f);
    __syncthreads();

    float4 g4 = ((const float4*)gamma)[tid];
    float4 b4 = ((const float4*)beta)[tid];
    float tl[4];
    tl[0] = dx0 * rstd * g4.x + b4.x;
    tl[1] = dx1 * rstd * g4.y + b4.y;
    tl[2] = dx2 * rstd * g4.z + b4.z;
    tl[3] = dx3 * rstd * g4.w + b4.w;
    ((float4*)(d_tokens_ln + (size_t)t * H))[tid] = make_float4(tl[0], tl[1], tl[2], tl[3]);

    int h0 = tid * 4;
    float acc[E];
    #pragma unroll
    for (int e = 0; e < E; e++) acc[e] = 0.0f;
    #pragma unroll
    for (int j = 0; j < 4; j++) {
        const float* rwr = rw + (size_t)(h0 + j) * E;
        #pragma unroll
        for (int e = 0; e < E; e++) acc[e] += tl[j] * rwr[e];
    }
    #pragma unroll
    for (int off = 16; off > 0; off >>= 1)
        #pragma unroll
        for (int e = 0; e < E; e++)
            acc[e] += __shfl_down_sync(0xffffffffu, acc[e], off);

    __shared__ float wlog[8][E];
    int warp = tid >> 5, lane = tid & 31;
    if (lane == 0)
        #pragma unroll
        for (int e = 0; e < E; e++) wlog[warp][e] = acc[e];
    __syncthreads();

    if (tid == 0) {
        float lg[E];
        #pragma unroll
        for (int e = 0; e < E; e++) {
            float sv = 0.0f;
            #pragma unroll
            for (int w = 0; w < 8; w++) sv += wlog[w][e];
            lg[e] = sv;
        }
        float mx = lg[0];
        #pragma unroll
        for (int e = 1; e < E; e++) mx = fmaxf(mx, lg[e]);
        float p[E];
        #pragma unroll
        for (int e = 0; e < E; e++) p[e] = expf(lg[e] - mx);
        int i0 = 0; float b0 = p[0];
        #pragma unroll
        for (int e = 1; e < E; e++) if (p[e] > b0) { b0 = p[e]; i0 = e; }
        int i1 = -1; float b1 = -1.0f;
        #pragma unroll
        for (int e = 0; e < E; e++) if (e != i0 && p[e] > b1) { b1 = p[e]; i1 = e; }
        float inv = 1.0f / (b0 + b1);
        d_idx[2 * t] = i0; d_idx[2 * t + 1] = i1;
        d_wts[2 * t] = b0 * inv; d_wts[2 * t + 1] = b1 * inv;
    }
}

// ---------------------------------------------------------------------------
// Kernel B: capacity assignment (stable), one block / expert
// ---------------------------------------------------------------------------
__global__ void __launch_bounds__(1024) assign_kernel()
{
    int e = blockIdx.x, tid = threadIdx.x;
    int lane = tid & 31, warp = tid >> 5;
    __shared__ int warpCnt[32];
    __shared__ int s_totalSel, s_runSel, s_runUnsel, s_chunkSel;

    int cnt = 0;
    for (int t = tid; t < T; t += 1024)
        cnt += (d_idx[2 * t] == e) | (d_idx[2 * t + 1] == e);
    #pragma unroll
    for (int off = 16; off > 0; off >>= 1) cnt += __shfl_down_sync(0xffffffffu, cnt, off);
    if (lane == 0) warpCnt[warp] = cnt;
    __syncthreads();
    if (tid == 0) {
        int sv = 0;
        for (int w = 0; w < 32; w++) sv += warpCnt[w];
        s_totalSel = sv; s_runSel = 0; s_runUnsel = 0;
    }
    __syncthreads();
    int totalSel = s_totalSel;

    for (int base = 0; base < T; base += 1024) {
        int t = base + tid;
        int m = (d_idx[2 * t] == e) | (d_idx[2 * t + 1] == e);
        unsigned bal = __ballot_sync(0xffffffffu, m);
        int wpre = __popc(bal & ((1u << lane) - 1u));
        if (lane == 0) warpCnt[warp] = __popc(bal);
        __syncthreads();
        if (tid == 0) {
            int sv = 0;
            for (int w = 0; w < 32; w++) { int c = warpCnt[w]; warpCnt[w] = sv; sv += c; }
            s_chunkSel = sv;
        }
        __syncthreads();
        int selPre = warpCnt[warp] + wpre;
        int rs = s_runSel, ru = s_runUnsel;
        int pos = m ? (rs + selPre) : (totalSel + ru + (tid - selPre));
        if (pos < CAP) { d_sel[e * CAP + pos] = t; d_valid[e * CAP + pos] = m; }
        __syncthreads();
        if (tid == 0) { s_runSel = rs + s_chunkSel; s_runUnsel = ru + (1024 - s_chunkSel); }
        __syncthreads();
    }
}

// ---------------------------------------------------------------------------
// Kernel C: gather + fp16 convert: xin_fp[ec][h]
// ---------------------------------------------------------------------------
__global__ void __launch_bounds__(128) gather_convert_kernel()
{
    int ec = blockIdx.x, tid = threadIdx.x;
    int v = d_valid[ec], s = d_sel[ec];
    float4 a = make_float4(0.f,0.f,0.f,0.f), b = a;
    if (v) {
        const float4* src = (const float4*)(d_tokens_ln + (size_t)s * H);
        a = src[tid * 2]; b = src[tid * 2 + 1];
    }
    float vv[8] = {a.x, a.y, a.z, a.w, b.x, b.y, b.z, b.w};
    alignas(16) __half o[8];
    #pragma unroll
    for (int j = 0; j < 8; j++) o[j] = __float2half(vv[j]);
    ((uint4*)(d_xin_fp + (size_t)ec * KA1 + tid * 8))[0] = *(const uint4*)o;
}

// ---------------------------------------------------------------------------
// Kernel D: gate/up transpose [E][H][F] -> [E][2F][H] fp16 (rows 2f+s)
// ---------------------------------------------------------------------------
__global__ void __launch_bounds__(256) conv_gateup_kernel(
    const float* __restrict__ wg, const float* __restrict__ wu)
{
    int f0 = blockIdx.x * 32, h0 = blockIdx.y * 64, e = blockIdx.z;
    __shared__ float sg[32][65], su[32][65];
    int t = threadIdx.x, fi = t & 31, hr = t >> 5;
    #pragma unroll
    for (int it = 0; it < 8; it++) {
        int hl = hr + it * 8;
        size_t base = ((size_t)e * H + h0 + hl) * F + f0 + fi;
        sg[fi][hl] = wg[base];
        su[fi][hl] = wu[base];
    }
    __syncthreads();
    #pragma unroll
    for (int it = 0; it < 2; it++) {                 // 64 rows * 8 units / 256
        int u = t + it * 256;
        int r = u >> 3, unit = u & 7;
        int fl = r >> 1, sfl = r & 1;
        const float (*sm)[65] = sfl ? su : sg;
        alignas(16) __half o[8];
        #pragma unroll
        for (int j = 0; j < 8; j++) o[j] = __float2half(sm[fl][unit * 8 + j]);
        ((uint4*)(d_wgu_fp + ((size_t)e * NB1 + 2 * f0 + r) * KA1
                  + h0 + unit * 8))[0] = *(const uint4*)o;
    }
}

// ---------------------------------------------------------------------------
// Kernel E: down transpose [E][F][H] -> [E][H][F] fp16
// ---------------------------------------------------------------------------
__global__ void __launch_bounds__(256) conv_down_kernel(const float* __restrict__ wd)
{
    int f0 = blockIdx.x * 64, h0 = blockIdx.y * 32, e = blockIdx.z;
    __shared__ float sd[32][65];
    int t = threadIdx.x, hl = t & 31, fr = t >> 5;
    #pragma unroll
    for (int it = 0; it < 8; it++) {
        int fl = fr + it * 8;
        sd[hl][fl] = wd[((size_t)e * F + f0 + fl) * H + h0 + hl];
    }
    __syncthreads();
    {                                                // 32 rows * 8 units = 256
        int r = t >> 3, unit = t & 7;
        alignas(16) __half o[8];
        #pragma unroll
        for (int j = 0; j < 8; j++) o[j] = __float2half(sd[r][unit * 8 + j]);
        ((uint4*)(d_wd_fp + ((size_t)e * NB2 + h0 + r) * KA2
                  + f0 + unit * 8))[0] = *(const uint4*)o;
    }
}

// ---------------------------------------------------------------------------
// mma.sync fp16 GEMM: 128x128 CTA tile, BK=32, 8 warps, 4-stage cp.async.
// Grid: (m-tiles, n-tiles, E) — m fastest so B n-slices stay hot in L2.
// GATEUP epilogue: silu(g)*u -> fp16 -> smem stage -> coalesced STG.
// ---------------------------------------------------------------------------
constexpr int STAGE_BYTES = 20480;            // A 128*80 + B 128*80
constexpr int GEMM_SMEM   = 4 * STAGE_BYTES;  // 81920

template<int KT, int NB, bool GATEUP>
__global__ void __launch_bounds__(256, 2) moe_gemm_kernel()
{
    constexpr int NC = KT / 32;
    extern __shared__ char smem_raw[];
    uint32_t sb = smem_u32(smem_raw);
    int tid = threadIdx.x, wid = tid >> 5, lane = tid & 31;
    int e = blockIdx.z, m0 = blockIdx.x * 128, n0 = blockIdx.y * 128;
    int wm0 = (wid & 3) * 32, wn0 = (wid >> 2) * 64;

    const __half* Arow =
        (GATEUP ? d_xin_fp : d_act_fp) + ((size_t)e * CAP + m0) * KT;
    const __half* Brow =
        (GATEUP ? d_wgu_fp : d_wd_fp) + ((size_t)e * NB + n0) * KT;

    float acc[2][8][4] = {};

    auto loadst = [&](int s, int chunk) {
        uint32_t abase = sb + s * STAGE_BYTES;
        uint32_t bbase = abase + 10240;
        const char* ag = (const char*)Arow + chunk * 64;
        const char* bg = (const char*)Brow + chunk * 64;
        #pragma unroll
        for (int it = 0; it < 2; it++) {
            int u = tid + it * 256; int row = u >> 2, c = u & 3;
            CP_ASYNC16(abase + row * 80 + c * 16, ag + (size_t)row * (KT * 2) + c * 16);
        }
        #pragma unroll
        for (int it = 0; it < 2; it++) {
            int u = tid + it * 256; int row = u >> 2, c = u & 3;
            CP_ASYNC16(bbase + row * 80 + c * 16, bg + (size_t)row * (KT * 2) + c * 16);
        }
        CP_COMMIT();
    };

    #pragma unroll
    for (int s = 0; s < 4; s++) loadst(s, s);

    for (int i = 0; i < NC; i++) {
        int s = i & 3;
        CP_WAIT3();
        __syncthreads();
        uint32_t abase = sb + s * STAGE_BYTES;
        uint32_t bbase = abase + 10240;
        #pragma unroll
        for (int kk = 0; kk < 2; kk++) {
            uint32_t a[2][4];
            #pragma unroll
            for (int ms = 0; ms < 2; ms++) {
                uint32_t ad = abase + (wm0 + ms * 16 + (lane & 15)) * 80
                            + (kk * 2 + (lane >> 4)) * 16;
                ldmx4(a[ms][0], a[ms][1], a[ms][2], a[ms][3], ad);
            }
            #pragma unroll
            for (int np = 0; np < 4; np++) {
                uint32_t b0, b1, b2, b3;
                uint32_t bd = bbase + (wn0 + np * 16 + (lane & 7) + ((lane >> 4) << 3)) * 80
                            + (kk * 2 + ((lane >> 3) & 1)) * 16;
                ldmx4(b0, b1, b2, b3, bd);
                #pragma unroll
                for (int ms = 0; ms < 2; ms++) {
                    mma_f16(acc[ms][np * 2],     a[ms][0], a[ms][1], a[ms][2], a[ms][3], b0, b1);
                    mma_f16(acc[ms][np * 2 + 1], a[ms][0], a[ms][1], a[ms][2], a[ms][3], b2, b3);
                }
            }
        }
        __syncthreads();
        if (i + 4 < NC) loadst(s, i + 4); else CP_COMMIT();
    }

    // -------- epilogue --------
    if (GATEUP) {
        // silu(g)*u -> fp16 staged in smem (128 x 64), then coalesced STG
        __syncthreads();
        __half* sact = (__half*)smem_raw;
        #pragma unroll
        for (int ms = 0; ms < 2; ms++) {
            #pragma unroll
            for (int np = 0; np < 8; np++) {
                int f_l = (wn0 >> 1) + np * 4 + (lane & 3);
                #pragma unroll
                for (int h = 0; h < 2; h++) {
                    int row_l = wm0 + ms * 16 + (lane >> 2) + h * 8;
                    float g  = acc[ms][np][2 * h];
                    float uu = acc[ms][np][2 * h + 1];
                    float av = (g / (1.0f + __expf(-g))) * uu;
                    sact[row_l * 64 + f_l] = __float2half(av);
                }
            }
        }
        __syncthreads();
        int row = tid >> 1, half = tid & 1;
        const uint4* src = (const uint4*)(sact + row * 64) + half * 4;
        uint4* dst = (uint4*)(d_act_fp + ((size_t)e * CAP + m0 + row) * KA2
                              + (n0 >> 1)) + half * 4;
        #pragma unroll
        for (int q = 0; q < 4; q++) dst[q] = src[q];
    } else {
        #pragma unroll
        for (int ms = 0; ms < 2; ms++) {
            #pragma unroll
            for (int np = 0; np < 8; np++) {
                int r0 = m0 + wm0 + ms * 16 + (lane >> 2);
                int nc = n0 + wn0 + np * 8 + (lane & 3) * 2;
                #pragma unroll
                for (int h = 0; h < 2; h++) {
                    int row = r0 + h * 8;
                    float2* p = (float2*)(d_eout + ((size_t)e * CAP + row) * H + nc);
                    *p = make_float2(acc[ms][np][2 * h], acc[ms][np][2 * h + 1]);
                }
            }
        }
    }
}

// ---------------------------------------------------------------------------
// Kernel F: combine
// ---------------------------------------------------------------------------
__global__ void __launch_bounds__(256) combine_kernel(
    const float* __restrict__ x, float* __restrict__ out)
{
    int i = blockIdx.x * 256 + threadIdx.x;
    int h4 = i & (H / 4 - 1);
    int t  = i >> 8;
    int slot = min(t, CAP - 1);
    int i0 = d_idx[2 * t], i1 = d_idx[2 * t + 1];
    float w0 = d_wts[2 * t], w1 = d_wts[2 * t + 1];
    const float4* e4 = (const float4*)d_eout;
    float4 a  = ((const float4*)x)[i];
    float4 g0 = e4[((size_t)i0 * CAP + slot) * (H / 4) + h4];
    float4 g1 = e4[((size_t)i1 * CAP + slot) * (H / 4) + h4];
    float4 o;
    o.x = a.x + w0 * g0.x + w1 * g1.x;
    o.y = a.y + w0 * g0.y + w1 * g1.y;
    o.z = a.z + w0 * g0.z + w1 * g1.z;
    o.w = a.w + w0 * g0.w + w1 * g1.w;
    ((float4*)out)[i] = o;
}

// ---------------------------------------------------------------------------
// Launch
// ---------------------------------------------------------------------------
extern "C" void kernel_launch(void* const* d_in, const int* in_sizes, int n_in,
                              void* d_out, int out_size)
{
    const float* x     = (const float*)d_in[0];
    const float* rw    = (const float*)d_in[1];
    const float* wg    = (const float*)d_in[2];
    const float* wu    = (const float*)d_in[3];
    const float* wd    = (const float*)d_in[4];
    const float* gamma = (const float*)d_in[5];
    const float* beta  = (const float*)d_in[6];
    float*       out   = (float*)d_out;

    cudaFuncSetAttribute(moe_gemm_kernel<KA1, NB1, true>,
                         cudaFuncAttributeMaxDynamicSharedMemorySize, GEMM_SMEM);
    cudaFuncSetAttribute(moe_gemm_kernel<KA2, NB2, false>,
                         cudaFuncAttributeMaxDynamicSharedMemorySize, GEMM_SMEM);

    ln_router_kernel<<<T, 256>>>(x, rw, gamma, beta);
    assign_kernel<<<E, 1024>>>();
    conv_gateup_kernel<<<dim3(F / 32, H / 64, E), 256>>>(wg, wu);
    conv_down_kernel<<<dim3(F / 64, H / 32, E), 256>>>(wd);
    gather_convert_kernel<<<E * CAP, 128>>>();
    moe_gemm_kernel<KA1, NB1, true ><<<dim3(CAP / 128, NB1 / 128, E), 256, GEMM_SMEM>>>();
    moe_gemm_kernel<KA2, NB2, false><<<dim3(CAP / 128, NB2 / 128, E), 256, GEMM_SMEM>>>();
    combine_kernel<<<(T * H / 4) / 256, 256>>>(x, out);
}